// round 2
// baseline (speedup 1.0000x reference)
#include <cuda_runtime.h>
#include <math.h>
#include <stdint.h>

#define NIMG   2
#define TCAND  4768           // 4*1000 + 768
#define NWORDS 149            // 4768/32 exactly
#define SMAXX  196608         // max HWA (level p2)
#define SCALE_CLAMP 4.135166556742356f

// ------------------ static device scratch (no runtime allocs) ------------------
__device__ float    g_t[33554432];            // 2*256*65536 conv output (reused per level)
__device__ float    g_scores[NIMG * SMAXX];
__device__ float4   g_boxes [NIMG * SMAXX];
__device__ unsigned g_hist[NIMG * 256];
__device__ unsigned g_prefix[NIMG];
__device__ unsigned g_krem[NIMG];
__device__ unsigned g_kth[NIMG];
__device__ unsigned g_needed[NIMG];
__device__ float    g_cand_s[NIMG * TCAND];
__device__ float4   g_cand_b[NIMG * TCAND];
__device__ float    g_sorted_s[NIMG * TCAND];
__device__ float4   g_sorted_b[NIMG * TCAND];
__device__ float4   g_sorted_ob[NIMG * TCAND];
__device__ unsigned g_validw[NIMG * NWORDS];
__device__ unsigned g_mask[NIMG * TCAND * NWORDS];   // suppression bits, j>i only

// ------------------ helpers ------------------
__device__ __forceinline__ unsigned f2key(float f) {
    unsigned u = __float_as_uint(f);
    return (u & 0x80000000u) ? ~u : (u | 0x80000000u);
}
__device__ __forceinline__ float clip1024(float v) { return fminf(fmaxf(v, 0.f), 1024.f); }

// ------------------ conv3x3 SAME + bias + relu (implicit GEMM, fp32) ------------------
__global__ __launch_bounds__(256) void conv3x3_relu(
    const float* __restrict__ in, const float* __restrict__ wgt,
    const float* __restrict__ bias, int H, int W)
{
    const int HW  = H * W;
    const int n   = blockIdx.z;
    const int co0 = blockIdx.y * 128;
    const int p0  = blockIdx.x * 128;
    const float* inN = in + (size_t)n * 256 * HW;

    __shared__ float As[8][128];
    __shared__ float Bs[8][132];

    const int tid = threadIdx.x;
    const int tx = tid & 15, ty = tid >> 4;

    float acc[8][8];
#pragma unroll
    for (int i = 0; i < 8; i++)
#pragma unroll
        for (int j = 0; j < 8; j++) acc[i][j] = 0.f;

    const int mA   = tid >> 1;        // 0..127
    const int kA   = (tid & 1) * 4;   // 0 or 4
    const int ppB  = tid & 127;
    const int kkB0 = (tid >> 7) * 4;  // 0 or 4

    const int p   = p0 + ppB;
    const int y0p = p / W;
    const int x0p = p - y0p * W;

    for (int k0 = 0; k0 < 2304; k0 += 8) {
        float4 av = *reinterpret_cast<const float4*>(wgt + (size_t)(co0 + mA) * 2304 + k0 + kA);
        As[kA + 0][mA] = av.x; As[kA + 1][mA] = av.y;
        As[kA + 2][mA] = av.z; As[kA + 3][mA] = av.w;
#pragma unroll
        for (int q = 0; q < 4; q++) {
            int kk = kkB0 + q;
            int k  = k0 + kk;
            int ci = k / 9;
            int r  = k - ci * 9;
            int ky = r / 3;
            int kx = r - ky * 3;
            int yy = y0p + ky - 1;
            int xx = x0p + kx - 1;
            float v = 0.f;
            if ((unsigned)yy < (unsigned)H && (unsigned)xx < (unsigned)W)
                v = inN[(size_t)ci * HW + yy * W + xx];
            Bs[kk][ppB] = v;
        }
        __syncthreads();
#pragma unroll
        for (int kk = 0; kk < 8; kk++) {
            float4 a0 = *reinterpret_cast<const float4*>(&As[kk][ty * 8]);
            float4 a1 = *reinterpret_cast<const float4*>(&As[kk][ty * 8 + 4]);
            float4 b0 = *reinterpret_cast<const float4*>(&Bs[kk][tx * 8]);
            float4 b1 = *reinterpret_cast<const float4*>(&Bs[kk][tx * 8 + 4]);
            float a[8] = {a0.x, a0.y, a0.z, a0.w, a1.x, a1.y, a1.z, a1.w};
            float b[8] = {b0.x, b0.y, b0.z, b0.w, b1.x, b1.y, b1.z, b1.w};
#pragma unroll
            for (int i = 0; i < 8; i++)
#pragma unroll
                for (int j = 0; j < 8; j++)
                    acc[i][j] = fmaf(a[i], b[j], acc[i][j]);
        }
        __syncthreads();
    }
#pragma unroll
    for (int i = 0; i < 8; i++) {
        int co = co0 + ty * 8 + i;
        float bb = bias[co];
        float* op = g_t + ((size_t)n * 256 + co) * HW + p0 + tx * 8;
#pragma unroll
        for (int j = 0; j < 8; j++) {
            float v = acc[i][j] + bb;
            op[j] = v > 0.f ? v : 0.f;
        }
    }
}

// ------------------ head: 15 dot products/pixel + anchor decode + clip ------------------
__global__ __launch_bounds__(256) void head_kernel(
    const float* __restrict__ w_obj, const float* __restrict__ b_obj,
    const float* __restrict__ w_delta, const float* __restrict__ b_delta,
    int H, int W, float stride,
    double cw0, double ch0, double cw1, double ch1, double cw2, double ch2)
{
    __shared__ float sw[15][256];
    const int HW = H * W;
    const int n = blockIdx.y;
    const int p = blockIdx.x * 256 + threadIdx.x;

    for (int i = threadIdx.x; i < 15 * 256; i += 256) {
        int row = i >> 8, c = i & 255;
        sw[row][c] = (row < 3) ? w_obj[row * 256 + c] : w_delta[(row - 3) * 256 + c];
    }
    __syncthreads();
    if (p >= HW) return;

    float acc[15];
#pragma unroll
    for (int i = 0; i < 15; i++) acc[i] = 0.f;

    const float* tp = g_t + (size_t)n * 256 * HW + p;
    for (int c = 0; c < 256; c++) {
        float v = tp[(size_t)c * HW];
#pragma unroll
        for (int i = 0; i < 15; i++) acc[i] = fmaf(v, sw[i][c], acc[i]);
    }

    float gx = (float)(p % W) * stride;
    float gy = (float)(p / W) * stride;
    double CW[3] = {cw0, cw1, cw2};
    double CH[3] = {ch0, ch1, ch2};
#pragma unroll
    for (int a = 0; a < 3; a++) {
        float s  = acc[a] + b_obj[a];
        float dx = acc[3 + a * 4 + 0] + b_delta[a * 4 + 0];
        float dy = acc[3 + a * 4 + 1] + b_delta[a * 4 + 1];
        float dw = fminf(acc[3 + a * 4 + 2] + b_delta[a * 4 + 2], SCALE_CLAMP);
        float dh = fminf(acc[3 + a * 4 + 3] + b_delta[a * 4 + 3], SCALE_CLAMP);
        // anchors: f64 cell added to f32 shift, then cast to f32 (matches numpy/jnp)
        float x0 = (float)((double)gx + CW[a]);
        float x1 = (float)((double)gx - CW[a]);
        float y0 = (float)((double)gy + CH[a]);
        float y1 = (float)((double)gy - CH[a]);
        float aw = x1 - x0, ah = y1 - y0;
        float acx = x0 + 0.5f * aw, acy = y0 + 0.5f * ah;
        float pcx = dx * aw + acx;
        float pcy = dy * ah + acy;
        float pw = expf(dw) * aw;
        float ph = expf(dh) * ah;
        float4 bx;
        bx.x = clip1024(pcx - 0.5f * pw);
        bx.y = clip1024(pcy - 0.5f * ph);
        bx.z = clip1024(pcx + 0.5f * pw);
        bx.w = clip1024(pcy + 0.5f * ph);
        int idx = n * SMAXX + p * 3 + a;
        g_scores[idx] = s;
        g_boxes[idx]  = bx;
    }
}

// ------------------ radix-select of k-th largest (4 rounds x 8 bits) ------------------
__global__ void init_select(int k) {
    int n = blockIdx.x;
    if (threadIdx.x == 0) { g_prefix[n] = 0; g_krem[n] = (unsigned)k; }
    g_hist[n * 256 + threadIdx.x] = 0;
}

__global__ void hist_kernel(int L, int round) {
    __shared__ unsigned sh[256];
    int n = blockIdx.y;
    sh[threadIdx.x] = 0;
    __syncthreads();
    unsigned pfx = g_prefix[n];
    int shift = 24 - 8 * round;
    unsigned maskhi = (round == 0) ? 0u : (0xFFFFFFFFu << (shift + 8));
    for (int i = blockIdx.x * blockDim.x + threadIdx.x; i < L; i += gridDim.x * blockDim.x) {
        unsigned key = f2key(g_scores[n * SMAXX + i]);
        if (((key ^ pfx) & maskhi) == 0)
            atomicAdd(&sh[(key >> shift) & 255], 1u);
    }
    __syncthreads();
    if (sh[threadIdx.x]) atomicAdd(&g_hist[n * 256 + threadIdx.x], sh[threadIdx.x]);
}

__global__ void pick_kernel(int round) {
    int n = blockIdx.x;
    __shared__ unsigned h[256];
    h[threadIdx.x] = g_hist[n * 256 + threadIdx.x];
    __syncthreads();
    g_hist[n * 256 + threadIdx.x] = 0;   // clear for next round
    if (threadIdx.x == 0) {
        int shift = 24 - 8 * round;
        unsigned kr = g_krem[n];
        unsigned cum = 0;
        int bin = 255;
        for (; bin > 0; bin--) {
            unsigned c = h[bin];
            if (cum + c >= kr) break;
            cum += c;
        }
        kr -= cum;
        unsigned pfx = g_prefix[n] | ((unsigned)bin << shift);
        g_prefix[n] = pfx;
        g_krem[n] = kr;
        if (round == 3) { g_kth[n] = pfx; g_needed[n] = kr; }
    }
}

// ------------------ compaction: exact top-k SET (ties at kth -> lowest index) ------------------
__global__ __launch_bounds__(1024) void compact_kernel(int L, int k, int lvl_off) {
    int n = blockIdx.x;
    unsigned kth = g_kth[n];
    int needed = (int)g_needed[n];
    int G = k - needed;

    __shared__ unsigned wg[32], we[32];
    __shared__ int baseg, basee, totg, tote;
    if (threadIdx.x == 0) { baseg = 0; basee = 0; }
    __syncthreads();
    int lane = threadIdx.x & 31, w = threadIdx.x >> 5;

    for (int start = 0; start < L; start += 1024) {
        int i = start + threadIdx.x;
        bool gt = false, eq = false;
        float sc = 0.f;
        if (i < L) {
            sc = g_scores[n * SMAXX + i];
            unsigned key = f2key(sc);
            gt = key > kth;
            eq = (key == kth);
        }
        unsigned bg = __ballot_sync(0xffffffffu, gt);
        unsigned be = __ballot_sync(0xffffffffu, eq);
        if (lane == 0) { wg[w] = __popc(bg); we[w] = __popc(be); }
        __syncthreads();
        if (threadIdx.x < 32) {
            unsigned vg = wg[threadIdx.x], ve = we[threadIdx.x];
            unsigned ig = vg, ie = ve;
#pragma unroll
            for (int o = 1; o < 32; o <<= 1) {
                unsigned tg = __shfl_up_sync(0xffffffffu, ig, o);
                unsigned te = __shfl_up_sync(0xffffffffu, ie, o);
                if ((int)threadIdx.x >= o) { ig += tg; ie += te; }
            }
            wg[threadIdx.x] = ig - vg;
            we[threadIdx.x] = ie - ve;
            if (threadIdx.x == 31) { totg = (int)ig; tote = (int)ie; }
        }
        __syncthreads();
        if (gt) {
            int pos = baseg + (int)wg[w] + __popc(bg & ((1u << lane) - 1));
            g_cand_s[n * TCAND + lvl_off + pos] = sc;
            g_cand_b[n * TCAND + lvl_off + pos] = g_boxes[n * SMAXX + i];
        }
        if (eq) {
            int rank = basee + (int)we[w] + __popc(be & ((1u << lane) - 1));
            if (rank < needed) {
                int pos = G + rank;
                g_cand_s[n * TCAND + lvl_off + pos] = sc;
                g_cand_b[n * TCAND + lvl_off + pos] = g_boxes[n * SMAXX + i];
            }
        }
        __syncthreads();
        if (threadIdx.x == 0) { baseg += totg; basee += tote; }
        __syncthreads();
    }
}

// ------------------ per-image bitonic sort (score desc, idx asc) ------------------
__global__ __launch_bounds__(1024) void sort_kernel() {
    extern __shared__ unsigned long long keys[];   // 8192 * 8B
    int n = blockIdx.x;
    for (int i = threadIdx.x; i < 8192; i += 1024) {
        unsigned long long kk;
        if (i < TCAND) {
            unsigned sk = f2key(g_cand_s[n * TCAND + i]);
            kk = ((unsigned long long)(~sk) << 32) | (unsigned)i;
        } else kk = ~0ULL;
        keys[i] = kk;
    }
    for (int k = 2; k <= 8192; k <<= 1) {
        for (int j = k >> 1; j > 0; j >>= 1) {
            __syncthreads();
            for (int i = threadIdx.x; i < 8192; i += 1024) {
                int ixj = i ^ j;
                if (ixj > i) {
                    unsigned long long a = keys[i], b = keys[ixj];
                    bool up = ((i & k) == 0);
                    if ((a > b) == up) { keys[i] = b; keys[ixj] = a; }
                }
            }
        }
    }
    __syncthreads();
    // gather sorted arrays, offset boxes, valid bits
    for (int i = threadIdx.x; i < TCAND; i += 1024) {
        int j = (int)(unsigned)(keys[i] & 0xffffffffu);
        float s = g_cand_s[n * TCAND + j];
        float4 b = g_cand_b[n * TCAND + j];
        int lvl = (j < 4000) ? (j / 1000) : 4;
        float off = (float)lvl * 1025.0f;
        float4 ob = make_float4(b.x + off, b.y + off, b.z + off, b.w + off);
        g_sorted_s[n * TCAND + i] = s;
        g_sorted_b[n * TCAND + i] = b;
        g_sorted_ob[n * TCAND + i] = ob;
        bool valid = (b.z - b.x > 0.f) && (b.w - b.y > 0.f);
        unsigned bal = __ballot_sync(0xffffffffu, valid);
        if ((threadIdx.x & 31) == 0) g_validw[n * NWORDS + (i >> 5)] = bal;
    }
}

// ------------------ IoU suppression bit-matrix (j > i only) ------------------
__global__ __launch_bounds__(256) void iou_kernel() {
    int n = blockIdx.z;
    int i = blockIdx.y;
    int j = blockIdx.x * 256 + threadIdx.x;
    float4 bi = g_sorted_ob[n * TCAND + i];
    bool sup = false;
    if (j < TCAND && j > i) {
        float4 bj = g_sorted_ob[n * TCAND + j];
        float areai = (bi.z - bi.x) * (bi.w - bi.y);
        float areaj = (bj.z - bj.x) * (bj.w - bj.y);
        float ltx = fmaxf(bi.x, bj.x), lty = fmaxf(bi.y, bj.y);
        float rbx = fminf(bi.z, bj.z), rby = fminf(bi.w, bj.w);
        float iw = fmaxf(rbx - ltx, 0.f), ih = fmaxf(rby - lty, 0.f);
        float inter = iw * ih;
        float uni = areai + areaj - inter;
        float iou = (uni > 0.f) ? (inter / uni) : 0.f;
        sup = iou > 0.7f;
    }
    unsigned bal = __ballot_sync(0xffffffffu, sup);
    if ((threadIdx.x & 31) == 0) {
        int wq = j >> 5;
        if (wq < NWORDS) g_mask[((size_t)n * TCAND + i) * NWORDS + wq] = bal;
    }
}

// ------------------ sequential greedy scan + emission (1 warp / image) ------------------
__global__ void nms_scan(float* __restrict__ out) {
    int n = blockIdx.x;
    int lane = threadIdx.x;    // 32 threads
    unsigned keep[5];
#pragma unroll
    for (int q = 0; q < 5; q++) {
        int w = lane * 5 + q;
        keep[q] = (w < NWORDS) ? 0xFFFFFFFFu : 0u;
    }
    const unsigned* mask = g_mask + (size_t)n * TCAND * NWORDS;
    const int NCH = TCAND / 8;   // 596
    unsigned cur[8][5], nxt[8][5];
#pragma unroll
    for (int t = 0; t < 8; t++)
#pragma unroll
        for (int q = 0; q < 5; q++) {
            int w = lane * 5 + q;
            cur[t][q] = (w < NWORDS) ? mask[(size_t)t * NWORDS + w] : 0u;
        }
    for (int c = 0; c < NCH; c++) {
        if (c + 1 < NCH) {
            int base = (c + 1) * 8;
#pragma unroll
            for (int t = 0; t < 8; t++)
#pragma unroll
                for (int q = 0; q < 5; q++) {
                    int w = lane * 5 + q;
                    nxt[t][q] = (w < NWORDS) ? mask[(size_t)(base + t) * NWORDS + w] : 0u;
                }
        }
#pragma unroll
        for (int t = 0; t < 8; t++) {
            int i = c * 8 + t;
            int wi = i >> 5;
            int owner = wi / 5;
            int qi = wi - owner * 5;
            unsigned kw;
            switch (qi) {
                case 0: kw = keep[0]; break;
                case 1: kw = keep[1]; break;
                case 2: kw = keep[2]; break;
                case 3: kw = keep[3]; break;
                default: kw = keep[4]; break;
            }
            unsigned word = __shfl_sync(0xffffffffu, kw, owner);
            if ((word >> (i & 31)) & 1u) {
#pragma unroll
                for (int q = 0; q < 5; q++) keep[q] &= ~cur[t][q];
            }
        }
#pragma unroll
        for (int t = 0; t < 8; t++)
#pragma unroll
            for (int q = 0; q < 5; q++) cur[t][q] = nxt[t][q];
    }
    // final keep &= valid
#pragma unroll
    for (int q = 0; q < 5; q++) {
        int w = lane * 5 + q;
        if (w < NWORDS) keep[q] &= g_validw[n * NWORDS + w];
    }
    // prefix across lanes
    int mycnt = 0;
#pragma unroll
    for (int q = 0; q < 5; q++) mycnt += __popc(keep[q]);
    int incl = mycnt;
#pragma unroll
    for (int o = 1; o < 32; o <<= 1) {
        int t = __shfl_up_sync(0xffffffffu, incl, o);
        if (lane >= o) incl += t;
    }
    int nk = __shfl_sync(0xffffffffu, incl, 31);
    int run = incl - mycnt;
    float ninf = __int_as_float((int)0xff800000u);
    float* outS = out + 8000;
#pragma unroll
    for (int q = 0; q < 5; q++) {
        int w = lane * 5 + q;
        if (w >= NWORDS) continue;
        unsigned kwv = keep[q];
        for (int b = 0; b < 32; b++) {
            int i = w * 32 + b;
            int ones_before = run + __popc(kwv & ((1u << b) - 1));
            bool kept = (kwv >> b) & 1u;
            int pos = kept ? ones_before : (nk + (i - ones_before));
            if (pos < 1000) {
                float4 bx = g_sorted_b[n * TCAND + i];
                float* ob = out + ((size_t)n * 1000 + pos) * 4;
                ob[0] = bx.x; ob[1] = bx.y; ob[2] = bx.z; ob[3] = bx.w;
                outS[n * 1000 + pos] = kept ? g_sorted_s[n * TCAND + i] : ninf;
            }
        }
        run += __popc(kwv);
    }
}

// ------------------ launch ------------------
extern "C" void kernel_launch(void* const* d_in, const int* in_sizes, int n_in,
                              void* d_out, int out_size) {
    (void)in_sizes; (void)n_in; (void)out_size;
    const float* feats[5] = {
        (const float*)d_in[0], (const float*)d_in[1], (const float*)d_in[2],
        (const float*)d_in[3], (const float*)d_in[4]
    };
    const float* w_conv  = (const float*)d_in[5];
    const float* b_conv  = (const float*)d_in[6];
    const float* w_obj   = (const float*)d_in[7];
    const float* b_obj   = (const float*)d_in[8];
    const float* w_delta = (const float*)d_in[9];
    const float* b_delta = (const float*)d_in[10];

    static const int   Hs[5]      = {256, 128, 64, 32, 16};
    static const int   strides[5] = {4, 8, 16, 32, 64};
    static const double sizes[5]  = {32.0, 64.0, 128.0, 256.0, 512.0};
    static const double ratios[3] = {0.5, 1.0, 2.0};

    for (int lvl = 0; lvl < 5; lvl++) {
        int H = Hs[lvl], W = Hs[lvl];
        int HW = H * W;
        int L = HW * 3;
        int k = (L < 1000) ? L : 1000;

        dim3 cg(HW / 128, 2, NIMG);
        conv3x3_relu<<<cg, 256>>>(feats[lvl], w_conv, b_conv, H, W);

        double area = sizes[lvl] * sizes[lvl];
        double cw[3], ch[3];
        for (int a = 0; a < 3; a++) {
            double w = sqrt(area / ratios[a]);
            double h = w * ratios[a];
            cw[a] = -w / 2.0;
            ch[a] = -h / 2.0;
        }
        dim3 hg((HW + 255) / 256, NIMG);
        head_kernel<<<hg, 256>>>(w_obj, b_obj, w_delta, b_delta, H, W,
                                 (float)strides[lvl],
                                 cw[0], ch[0], cw[1], ch[1], cw[2], ch[2]);

        init_select<<<NIMG, 256>>>(k);
        for (int r = 0; r < 4; r++) {
            hist_kernel<<<dim3(48, NIMG), 256>>>(L, r);
            pick_kernel<<<NIMG, 256>>>(r);
        }
        compact_kernel<<<NIMG, 1024>>>(L, k, lvl * 1000);
    }

    cudaFuncSetAttribute(sort_kernel, cudaFuncAttributeMaxDynamicSharedMemorySize, 65536);
    sort_kernel<<<NIMG, 1024, 65536>>>();
    iou_kernel<<<dim3((TCAND + 255) / 256, TCAND, NIMG), 256>>>();
    nms_scan<<<NIMG, 32>>>((float*)d_out);
}

// round 3
// speedup vs baseline: 1.0503x; 1.0503x over previous
#include <cuda_runtime.h>
#include <math.h>
#include <stdint.h>

#define NIMG   2
#define TCAND  4768           // 4*1000 + 768
#define NWORDS 149            // 4768/32 exactly
#define STOT   261888         // total anchors per image (sum HW*3)
#define SCALE_CLAMP 4.135166556742356f

// ------------------ static device scratch ------------------
__device__ float    g_t[44695552];            // 2*256*87296 conv outputs, all levels
__device__ float    g_scores[NIMG * STOT];
__device__ float4   g_boxes [NIMG * STOT];
__device__ unsigned g_hist[10 * 256];         // [lvl*2+n][256]
__device__ unsigned g_prefix[10];
__device__ unsigned g_krem[10];
__device__ unsigned g_kth[10];
__device__ unsigned g_needed[10];
__device__ float    g_cand_s[NIMG * TCAND];
__device__ float4   g_cand_b[NIMG * TCAND];
__device__ float    g_sorted_s[NIMG * TCAND];
__device__ float4   g_sorted_b[NIMG * TCAND];
__device__ float4   g_sorted_ob[NIMG * TCAND];
__device__ unsigned g_validw[NIMG * NWORDS];
__device__ unsigned g_mask[NIMG * TCAND * NWORDS];

// ------------------ level tables ------------------
__constant__ int   c_H[5]      = {256, 128, 64, 32, 16};
__constant__ int   c_HW[5]     = {65536, 16384, 4096, 1024, 256};
__constant__ int   c_cumHW[5]  = {0, 65536, 81920, 86016, 87040};
__constant__ float c_stride[5] = {4.f, 8.f, 16.f, 32.f, 64.f};
__constant__ int   c_soff[5]   = {0, 196608, 245760, 258048, 261120};
__constant__ int   c_L[5]      = {196608, 49152, 12288, 3072, 768};
__constant__ int   c_k[5]      = {1000, 1000, 1000, 1000, 768};

struct Feats { const float* p[5]; };
struct AnchorP { double cw[15]; double ch[15]; };   // [lvl*3+a]

// ------------------ helpers ------------------
__device__ __forceinline__ unsigned f2key(float f) {
    unsigned u = __float_as_uint(f);
    return (u & 0x80000000u) ? ~u : (u | 0x80000000u);
}
__device__ __forceinline__ float clip1024(float v) { return fminf(fmaxf(v, 0.f), 1024.f); }

__device__ __forceinline__ void ffma2(unsigned long long& d, unsigned long long a, unsigned long long b) {
    asm("fma.rn.f32x2 %0, %1, %2, %0;" : "+l"(d) : "l"(a), "l"(b));
}
__device__ __forceinline__ float2 unpack2(unsigned long long v) {
    float2 r;
    asm("mov.b64 {%0, %1}, %2;" : "=f"(r.x), "=f"(r.y) : "l"(v));
    return r;
}

// ------------------ fused all-level conv3x3 SAME + bias + relu (f32x2 implicit GEMM) ------------------
// grid: x = 682 pixel-tiles across levels (512,128,32,8,2), y = img, z = co half
__global__ __launch_bounds__(256, 2) void conv3x3_relu_all(
    Feats feats, const float* __restrict__ wgt, const float* __restrict__ bias)
{
    int bx = blockIdx.x;
    int lvl, pt;
    if      (bx < 512) { lvl = 0; pt = bx; }
    else if (bx < 640) { lvl = 1; pt = bx - 512; }
    else if (bx < 672) { lvl = 2; pt = bx - 640; }
    else if (bx < 680) { lvl = 3; pt = bx - 672; }
    else               { lvl = 4; pt = bx - 680; }
    const int H  = c_H[lvl];
    const int W  = H;
    const int HW = c_HW[lvl];
    const int n   = blockIdx.y;
    const int co0 = blockIdx.z * 128;
    const int p0  = pt * 128;
    const float* inN = feats.p[lvl] + (size_t)n * 256 * HW;
    float* tlev = g_t + (size_t)512 * c_cumHW[lvl];

    __shared__ __align__(16) float As2[8][256];   // duplicated pairs: [kk][2m]=[kk][2m+1]=w[m]
    __shared__ __align__(16) float Bs[8][132];

    const int tid = threadIdx.x;
    const int tx = tid & 15, ty = tid >> 4;

    unsigned long long acc2[8][4];
#pragma unroll
    for (int i = 0; i < 8; i++)
#pragma unroll
        for (int j = 0; j < 4; j++) acc2[i][j] = 0ULL;

    const int mA   = tid >> 1;        // 0..127
    const int kA   = (tid & 1) * 4;   // 0 or 4
    const int ppB  = tid & 127;
    const int kkB0 = (tid >> 7) * 4;  // 0 or 4

    const int p   = p0 + ppB;
    const int y0p = p / W;
    const int x0p = p - y0p * W;

    for (int k0 = 0; k0 < 2304; k0 += 8) {
        float4 av = *reinterpret_cast<const float4*>(wgt + (size_t)(co0 + mA) * 2304 + k0 + kA);
        float wv[4] = {av.x, av.y, av.z, av.w};
#pragma unroll
        for (int q = 0; q < 4; q++)
            *reinterpret_cast<float2*>(&As2[kA + q][2 * mA]) = make_float2(wv[q], wv[q]);
#pragma unroll
        for (int q = 0; q < 4; q++) {
            int kk = kkB0 + q;
            int k  = k0 + kk;
            int ci = k / 9;
            int r  = k - ci * 9;
            int ky = r / 3;
            int kx = r - ky * 3;
            int yy = y0p + ky - 1;
            int xx = x0p + kx - 1;
            float v = 0.f;
            if ((unsigned)yy < (unsigned)H && (unsigned)xx < (unsigned)W)
                v = inN[(size_t)ci * HW + yy * W + xx];
            Bs[kk][ppB] = v;
        }
        __syncthreads();
#pragma unroll
        for (int kk = 0; kk < 8; kk++) {
            unsigned long long a2[8], b2[4];
#pragma unroll
            for (int q = 0; q < 4; q++) {
                ulonglong2 t = *reinterpret_cast<const ulonglong2*>(&As2[kk][ty * 16 + q * 4]);
                a2[2 * q] = t.x; a2[2 * q + 1] = t.y;
            }
            {
                ulonglong2 t0 = *reinterpret_cast<const ulonglong2*>(&Bs[kk][tx * 8]);
                ulonglong2 t1 = *reinterpret_cast<const ulonglong2*>(&Bs[kk][tx * 8 + 4]);
                b2[0] = t0.x; b2[1] = t0.y; b2[2] = t1.x; b2[3] = t1.y;
            }
#pragma unroll
            for (int i = 0; i < 8; i++)
#pragma unroll
                for (int j = 0; j < 4; j++)
                    ffma2(acc2[i][j], a2[i], b2[j]);
        }
        __syncthreads();
    }
#pragma unroll
    for (int i = 0; i < 8; i++) {
        int co = co0 + ty * 8 + i;
        float bb = bias[co];
        float* op = tlev + ((size_t)(n * 256 + co)) * HW + p0 + tx * 8;
#pragma unroll
        for (int j = 0; j < 4; j++) {
            float2 v = unpack2(acc2[i][j]);
            float v0 = v.x + bb, v1 = v.y + bb;
            op[2 * j]     = v0 > 0.f ? v0 : 0.f;
            op[2 * j + 1] = v1 > 0.f ? v1 : 0.f;
        }
    }
}

// ------------------ fused all-level head + anchor decode + clip ------------------
// grid: x = 341 pixel-blocks (256,64,16,4,1), y = img
__global__ __launch_bounds__(256) void head_all(
    const float* __restrict__ w_obj, const float* __restrict__ b_obj,
    const float* __restrict__ w_delta, const float* __restrict__ b_delta,
    AnchorP ap)
{
    int bx = blockIdx.x;
    int lvl, pt;
    if      (bx < 256) { lvl = 0; pt = bx; }
    else if (bx < 320) { lvl = 1; pt = bx - 256; }
    else if (bx < 336) { lvl = 2; pt = bx - 320; }
    else if (bx < 340) { lvl = 3; pt = bx - 336; }
    else               { lvl = 4; pt = bx - 340; }
    const int HW = c_HW[lvl];
    const int W  = c_H[lvl];
    const float stride = c_stride[lvl];
    const int n = blockIdx.y;
    const int p = pt * 256 + threadIdx.x;

    __shared__ float sw[15][256];
    for (int i = threadIdx.x; i < 15 * 256; i += 256) {
        int row = i >> 8, c = i & 255;
        sw[row][c] = (row < 3) ? w_obj[row * 256 + c] : w_delta[(row - 3) * 256 + c];
    }
    __syncthreads();
    if (p >= HW) return;

    float acc[15];
#pragma unroll
    for (int i = 0; i < 15; i++) acc[i] = 0.f;

    const float* tp = g_t + (size_t)512 * c_cumHW[lvl] + (size_t)n * 256 * HW + p;
    for (int c = 0; c < 256; c++) {
        float v = tp[(size_t)c * HW];
#pragma unroll
        for (int i = 0; i < 15; i++) acc[i] = fmaf(v, sw[i][c], acc[i]);
    }

    float gx = (float)(p % W) * stride;
    float gy = (float)(p / W) * stride;
#pragma unroll
    for (int a = 0; a < 3; a++) {
        float s  = acc[a] + b_obj[a];
        float dx = acc[3 + a * 4 + 0] + b_delta[a * 4 + 0];
        float dy = acc[3 + a * 4 + 1] + b_delta[a * 4 + 1];
        float dw = fminf(acc[3 + a * 4 + 2] + b_delta[a * 4 + 2], SCALE_CLAMP);
        float dh = fminf(acc[3 + a * 4 + 3] + b_delta[a * 4 + 3], SCALE_CLAMP);
        double CW = ap.cw[lvl * 3 + a], CH = ap.ch[lvl * 3 + a];
        float x0 = (float)((double)gx + CW);
        float x1 = (float)((double)gx - CW);
        float y0 = (float)((double)gy + CH);
        float y1 = (float)((double)gy - CH);
        float aw = x1 - x0, ah = y1 - y0;
        float acx = x0 + 0.5f * aw, acy = y0 + 0.5f * ah;
        float pcx = dx * aw + acx;
        float pcy = dy * ah + acy;
        float pw = expf(dw) * aw;
        float ph = expf(dh) * ah;
        float4 bx4;
        bx4.x = clip1024(pcx - 0.5f * pw);
        bx4.y = clip1024(pcy - 0.5f * ph);
        bx4.z = clip1024(pcx + 0.5f * pw);
        bx4.w = clip1024(pcy + 0.5f * ph);
        int idx = n * STOT + c_soff[lvl] + p * 3 + a;
        g_scores[idx] = s;
        g_boxes[idx]  = bx4;
    }
}

// ------------------ level-parallel radix-select (k-th largest) ------------------
__global__ void init_select() {
    int s = blockIdx.x;              // lvl*2+n
    if (threadIdx.x == 0) { g_prefix[s] = 0; g_krem[s] = (unsigned)c_k[s >> 1]; }
    g_hist[s * 256 + threadIdx.x] = 0;
}

__global__ void hist_kernel(int round) {
    __shared__ unsigned sh[256];
    int n = blockIdx.y, lvl = blockIdx.z;
    int s = lvl * 2 + n;
    sh[threadIdx.x] = 0;
    __syncthreads();
    unsigned pfx = g_prefix[s];
    int shift = 24 - 8 * round;
    unsigned maskhi = (round == 0) ? 0u : (0xFFFFFFFFu << (shift + 8));
    int L = c_L[lvl];
    const float* sc = g_scores + n * STOT + c_soff[lvl];
    for (int i = blockIdx.x * blockDim.x + threadIdx.x; i < L; i += gridDim.x * blockDim.x) {
        unsigned key = f2key(sc[i]);
        if (((key ^ pfx) & maskhi) == 0)
            atomicAdd(&sh[(key >> shift) & 255], 1u);
    }
    __syncthreads();
    if (sh[threadIdx.x]) atomicAdd(&g_hist[s * 256 + threadIdx.x], sh[threadIdx.x]);
}

__global__ void pick_kernel(int round) {
    int s = blockIdx.x;
    __shared__ unsigned h[256];
    h[threadIdx.x] = g_hist[s * 256 + threadIdx.x];
    __syncthreads();
    g_hist[s * 256 + threadIdx.x] = 0;
    if (threadIdx.x == 0) {
        int shift = 24 - 8 * round;
        unsigned kr = g_krem[s];
        unsigned cum = 0;
        int bin = 255;
        for (; bin > 0; bin--) {
            unsigned c = h[bin];
            if (cum + c >= kr) break;
            cum += c;
        }
        kr -= cum;
        unsigned pfx = g_prefix[s] | ((unsigned)bin << shift);
        g_prefix[s] = pfx;
        g_krem[s] = kr;
        if (round == 3) { g_kth[s] = pfx; g_needed[s] = kr; }
    }
}

// ------------------ compaction: exact top-k SET (ties -> lowest index) ------------------
__global__ __launch_bounds__(1024) void compact_kernel() {
    int n = blockIdx.x, lvl = blockIdx.y;
    int s = lvl * 2 + n;
    int L = c_L[lvl], k = c_k[lvl], lvl_off = lvl * 1000;
    unsigned kth = g_kth[s];
    int needed = (int)g_needed[s];
    int G = k - needed;
    const float* scp = g_scores + n * STOT + c_soff[lvl];
    const float4* bxp = g_boxes + n * STOT + c_soff[lvl];

    __shared__ unsigned wg[32], we[32];
    __shared__ int baseg, basee, totg, tote;
    if (threadIdx.x == 0) { baseg = 0; basee = 0; }
    __syncthreads();
    int lane = threadIdx.x & 31, w = threadIdx.x >> 5;

    for (int start = 0; start < L; start += 1024) {
        int i = start + threadIdx.x;
        bool gt = false, eq = false;
        float sc = 0.f;
        if (i < L) {
            sc = scp[i];
            unsigned key = f2key(sc);
            gt = key > kth;
            eq = (key == kth);
        }
        unsigned bg = __ballot_sync(0xffffffffu, gt);
        unsigned be = __ballot_sync(0xffffffffu, eq);
        if (lane == 0) { wg[w] = __popc(bg); we[w] = __popc(be); }
        __syncthreads();
        if (threadIdx.x < 32) {
            unsigned vg = wg[threadIdx.x], ve = we[threadIdx.x];
            unsigned ig = vg, ie = ve;
#pragma unroll
            for (int o = 1; o < 32; o <<= 1) {
                unsigned tg = __shfl_up_sync(0xffffffffu, ig, o);
                unsigned te = __shfl_up_sync(0xffffffffu, ie, o);
                if ((int)threadIdx.x >= o) { ig += tg; ie += te; }
            }
            wg[threadIdx.x] = ig - vg;
            we[threadIdx.x] = ie - ve;
            if (threadIdx.x == 31) { totg = (int)ig; tote = (int)ie; }
        }
        __syncthreads();
        if (gt) {
            int pos = baseg + (int)wg[w] + __popc(bg & ((1u << lane) - 1));
            g_cand_s[n * TCAND + lvl_off + pos] = sc;
            g_cand_b[n * TCAND + lvl_off + pos] = bxp[i];
        }
        if (eq) {
            int rank = basee + (int)we[w] + __popc(be & ((1u << lane) - 1));
            if (rank < needed) {
                int pos = G + rank;
                g_cand_s[n * TCAND + lvl_off + pos] = sc;
                g_cand_b[n * TCAND + lvl_off + pos] = bxp[i];
            }
        }
        __syncthreads();
        if (threadIdx.x == 0) { baseg += totg; basee += tote; }
        __syncthreads();
    }
}

// ------------------ per-image bitonic sort (score desc, idx asc) ------------------
__global__ __launch_bounds__(1024) void sort_kernel() {
    extern __shared__ unsigned long long keys[];
    int n = blockIdx.x;
    for (int i = threadIdx.x; i < 8192; i += 1024) {
        unsigned long long kk;
        if (i < TCAND) {
            unsigned sk = f2key(g_cand_s[n * TCAND + i]);
            kk = ((unsigned long long)(~sk) << 32) | (unsigned)i;
        } else kk = ~0ULL;
        keys[i] = kk;
    }
    for (int k = 2; k <= 8192; k <<= 1) {
        for (int j = k >> 1; j > 0; j >>= 1) {
            __syncthreads();
            for (int i = threadIdx.x; i < 8192; i += 1024) {
                int ixj = i ^ j;
                if (ixj > i) {
                    unsigned long long a = keys[i], b = keys[ixj];
                    bool up = ((i & k) == 0);
                    if ((a > b) == up) { keys[i] = b; keys[ixj] = a; }
                }
            }
        }
    }
    __syncthreads();
    for (int i = threadIdx.x; i < TCAND; i += 1024) {
        int j = (int)(unsigned)(keys[i] & 0xffffffffu);
        float s = g_cand_s[n * TCAND + j];
        float4 b = g_cand_b[n * TCAND + j];
        int lvl = (j < 4000) ? (j / 1000) : 4;
        float off = (float)lvl * 1025.0f;
        float4 ob = make_float4(b.x + off, b.y + off, b.z + off, b.w + off);
        g_sorted_s[n * TCAND + i] = s;
        g_sorted_b[n * TCAND + i] = b;
        g_sorted_ob[n * TCAND + i] = ob;
        bool valid = (b.z - b.x > 0.f) && (b.w - b.y > 0.f);
        unsigned bal = __ballot_sync(0xffffffffu, valid);
        if ((threadIdx.x & 31) == 0) g_validw[n * NWORDS + (i >> 5)] = bal;
    }
}

// ------------------ IoU suppression bit-matrix (j > i only) ------------------
__global__ __launch_bounds__(256) void iou_kernel() {
    int n = blockIdx.z;
    int i = blockIdx.y;
    int j = blockIdx.x * 256 + threadIdx.x;
    float4 bi = g_sorted_ob[n * TCAND + i];
    bool sup = false;
    if (j < TCAND && j > i) {
        float4 bj = g_sorted_ob[n * TCAND + j];
        float areai = (bi.z - bi.x) * (bi.w - bi.y);
        float areaj = (bj.z - bj.x) * (bj.w - bj.y);
        float ltx = fmaxf(bi.x, bj.x), lty = fmaxf(bi.y, bj.y);
        float rbx = fminf(bi.z, bj.z), rby = fminf(bi.w, bj.w);
        float iw = fmaxf(rbx - ltx, 0.f), ih = fmaxf(rby - lty, 0.f);
        float inter = iw * ih;
        float uni = areai + areaj - inter;
        float iou = (uni > 0.f) ? (inter / uni) : 0.f;
        sup = iou > 0.7f;
    }
    unsigned bal = __ballot_sync(0xffffffffu, sup);
    if ((threadIdx.x & 31) == 0) {
        int wq = j >> 5;
        if (wq < NWORDS) g_mask[((size_t)n * TCAND + i) * NWORDS + wq] = bal;
    }
}

// ------------------ sequential greedy scan + ordered emission (1 warp / image) ------------------
__global__ void nms_scan(float* __restrict__ out) {
    int n = blockIdx.x;
    int lane = threadIdx.x;
    unsigned keep[5];
#pragma unroll
    for (int q = 0; q < 5; q++) {
        int w = lane * 5 + q;
        keep[q] = (w < NWORDS) ? 0xFFFFFFFFu : 0u;
    }
    const unsigned* mask = g_mask + (size_t)n * TCAND * NWORDS;
    const int NCH = TCAND / 8;
    unsigned cur[8][5], nxt[8][5];
#pragma unroll
    for (int t = 0; t < 8; t++)
#pragma unroll
        for (int q = 0; q < 5; q++) {
            int w = lane * 5 + q;
            cur[t][q] = (w < NWORDS) ? mask[(size_t)t * NWORDS + w] : 0u;
        }
    for (int c = 0; c < NCH; c++) {
        if (c + 1 < NCH) {
            int base = (c + 1) * 8;
#pragma unroll
            for (int t = 0; t < 8; t++)
#pragma unroll
                for (int q = 0; q < 5; q++) {
                    int w = lane * 5 + q;
                    nxt[t][q] = (w < NWORDS) ? mask[(size_t)(base + t) * NWORDS + w] : 0u;
                }
        }
#pragma unroll
        for (int t = 0; t < 8; t++) {
            int i = c * 8 + t;
            int wi = i >> 5;
            int owner = wi / 5;
            int qi = wi - owner * 5;
            unsigned kw;
            switch (qi) {
                case 0: kw = keep[0]; break;
                case 1: kw = keep[1]; break;
                case 2: kw = keep[2]; break;
                case 3: kw = keep[3]; break;
                default: kw = keep[4]; break;
            }
            unsigned word = __shfl_sync(0xffffffffu, kw, owner);
            if ((word >> (i & 31)) & 1u) {
#pragma unroll
                for (int q = 0; q < 5; q++) keep[q] &= ~cur[t][q];
            }
        }
#pragma unroll
        for (int t = 0; t < 8; t++)
#pragma unroll
            for (int q = 0; q < 5; q++) cur[t][q] = nxt[t][q];
    }
#pragma unroll
    for (int q = 0; q < 5; q++) {
        int w = lane * 5 + q;
        if (w < NWORDS) keep[q] &= g_validw[n * NWORDS + w];
    }
    int mycnt = 0;
#pragma unroll
    for (int q = 0; q < 5; q++) mycnt += __popc(keep[q]);
    int incl = mycnt;
#pragma unroll
    for (int o = 1; o < 32; o <<= 1) {
        int t = __shfl_up_sync(0xffffffffu, incl, o);
        if (lane >= o) incl += t;
    }
    int nk = __shfl_sync(0xffffffffu, incl, 31);
    int run = incl - mycnt;
    float ninf = __int_as_float((int)0xff800000u);
    float* outS = out + 8000;
#pragma unroll
    for (int q = 0; q < 5; q++) {
        int w = lane * 5 + q;
        if (w >= NWORDS) continue;
        unsigned kwv = keep[q];
        for (int b = 0; b < 32; b++) {
            int i = w * 32 + b;
            int ones_before = run + __popc(kwv & ((1u << b) - 1));
            bool kept = (kwv >> b) & 1u;
            int pos = kept ? ones_before : (nk + (i - ones_before));
            if (pos < 1000) {
                float4 bx = g_sorted_b[n * TCAND + i];
                float* ob = out + ((size_t)n * 1000 + pos) * 4;
                ob[0] = bx.x; ob[1] = bx.y; ob[2] = bx.z; ob[3] = bx.w;
                outS[n * 1000 + pos] = kept ? g_sorted_s[n * TCAND + i] : ninf;
            }
        }
        run += __popc(kwv);
    }
}

// ------------------ launch ------------------
extern "C" void kernel_launch(void* const* d_in, const int* in_sizes, int n_in,
                              void* d_out, int out_size) {
    (void)in_sizes; (void)n_in; (void)out_size;
    Feats feats;
    for (int i = 0; i < 5; i++) feats.p[i] = (const float*)d_in[i];
    const float* w_conv  = (const float*)d_in[5];
    const float* b_conv  = (const float*)d_in[6];
    const float* w_obj   = (const float*)d_in[7];
    const float* b_obj   = (const float*)d_in[8];
    const float* w_delta = (const float*)d_in[9];
    const float* b_delta = (const float*)d_in[10];

    static const double sizesT[5] = {32.0, 64.0, 128.0, 256.0, 512.0};
    static const double ratios[3] = {0.5, 1.0, 2.0};
    AnchorP ap;
    for (int l = 0; l < 5; l++) {
        double area = sizesT[l] * sizesT[l];
        for (int a = 0; a < 3; a++) {
            double w = sqrt(area / ratios[a]);
            double h = w * ratios[a];
            ap.cw[l * 3 + a] = -w / 2.0;
            ap.ch[l * 3 + a] = -h / 2.0;
        }
    }

    conv3x3_relu_all<<<dim3(682, NIMG, 2), 256>>>(feats, w_conv, b_conv);
    head_all<<<dim3(341, NIMG), 256>>>(w_obj, b_obj, w_delta, b_delta, ap);

    init_select<<<10, 256>>>();
    for (int r = 0; r < 4; r++) {
        hist_kernel<<<dim3(32, NIMG, 5), 256>>>(r);
        pick_kernel<<<10, 256>>>(r);
    }
    compact_kernel<<<dim3(NIMG, 5), 1024>>>();

    cudaFuncSetAttribute(sort_kernel, cudaFuncAttributeMaxDynamicSharedMemorySize, 65536);
    sort_kernel<<<NIMG, 1024, 65536>>>();
    iou_kernel<<<dim3((TCAND + 255) / 256, TCAND, NIMG), 256>>>();
    nms_scan<<<NIMG, 32>>>((float*)d_out);
}

// round 4
// speedup vs baseline: 1.3937x; 1.3269x over previous
#include <cuda_runtime.h>
#include <math.h>
#include <stdint.h>

#define NIMG   2
#define TCAND  4768           // 4*1000 + 768
#define NWORDS 149            // 4768/32 exactly
#define STOT   261888         // total anchors per image (sum HW*3)
#define SCALE_CLAMP 4.135166556742356f

// ------------------ static device scratch ------------------
__device__ float    g_t[44695552];            // 2*256*87296 conv outputs, all levels
__device__ float    g_scores[NIMG * STOT];
__device__ float4   g_boxes [NIMG * STOT];
__device__ unsigned g_hist[10 * 256];         // [lvl*2+n][256]
__device__ unsigned g_prefix[10];
__device__ unsigned g_krem[10];
__device__ unsigned g_kth[10];
__device__ unsigned g_needed[10];
__device__ float    g_cand_s[NIMG * TCAND];
__device__ float4   g_cand_b[NIMG * TCAND];
__device__ float    g_sorted_s[NIMG * TCAND];
__device__ float4   g_sorted_b[NIMG * TCAND];
__device__ float4   g_sorted_ob[NIMG * TCAND];
__device__ unsigned g_validw[NIMG * NWORDS];
__device__ unsigned g_mask[NIMG * TCAND * NWORDS];

// ------------------ level tables ------------------
__constant__ int   c_H[5]      = {256, 128, 64, 32, 16};
__constant__ int   c_HW[5]     = {65536, 16384, 4096, 1024, 256};
__constant__ int   c_cumHW[5]  = {0, 65536, 81920, 86016, 87040};
__constant__ float c_stride[5] = {4.f, 8.f, 16.f, 32.f, 64.f};
__constant__ int   c_soff[5]   = {0, 196608, 245760, 258048, 261120};
__constant__ int   c_L[5]      = {196608, 49152, 12288, 3072, 768};
__constant__ int   c_k[5]      = {1000, 1000, 1000, 1000, 768};

struct Feats { const float* p[5]; };
struct AnchorP { double cw[15]; double ch[15]; };   // [lvl*3+a]

// ------------------ helpers ------------------
__device__ __forceinline__ unsigned f2key(float f) {
    unsigned u = __float_as_uint(f);
    return (u & 0x80000000u) ? ~u : (u | 0x80000000u);
}
__device__ __forceinline__ float clip1024(float v) { return fminf(fmaxf(v, 0.f), 1024.f); }

__device__ __forceinline__ void ffma2(unsigned long long& d, unsigned long long a, unsigned long long b) {
    asm("fma.rn.f32x2 %0, %1, %2, %0;" : "+l"(d) : "l"(a), "l"(b));
}
__device__ __forceinline__ unsigned long long dup2(float x) {
    unsigned long long r;
    asm("mov.b64 %0, {%1, %1};" : "=l"(r) : "f"(x));
    return r;
}
__device__ __forceinline__ float2 unpack2(unsigned long long v) {
    float2 r;
    asm("mov.b64 {%0, %1}, %2;" : "=f"(r.x), "=f"(r.y) : "l"(v));
    return r;
}

// ------------------ fused all-level conv3x3 SAME + bias + relu (FFMA2 implicit GEMM) ------------------
// block tile: 256 co x 128 px, thread tile 16 co (8 f32x2 pairs) x 8 px.
// grid: x = 682 pixel-tiles (512,128,32,8,2), y = img
__global__ __launch_bounds__(256, 1) void conv3x3_relu_all(
    Feats feats, const float* __restrict__ wgt, const float* __restrict__ bias)
{
    int bx = blockIdx.x;
    int lvl, pt;
    if      (bx < 512) { lvl = 0; pt = bx; }
    else if (bx < 640) { lvl = 1; pt = bx - 512; }
    else if (bx < 672) { lvl = 2; pt = bx - 640; }
    else if (bx < 680) { lvl = 3; pt = bx - 672; }
    else               { lvl = 4; pt = bx - 680; }
    const int H  = c_H[lvl];
    const int W  = H;
    const int HW = c_HW[lvl];
    const int n  = blockIdx.y;
    const int p0 = pt * 128;
    const float* inN = feats.p[lvl] + (size_t)n * 256 * HW;
    float* tlev = g_t + (size_t)512 * c_cumHW[lvl];

    __shared__ __align__(16) float As[2][8][256];   // [stage][kk][co]
    __shared__ __align__(16) float Bs[2][8][128];   // [stage][kk][px]

    const int tid = threadIdx.x;
    const int tx = tid & 15, ty = tid >> 4;

    unsigned long long acc2[8][8];
#pragma unroll
    for (int i = 0; i < 8; i++)
#pragma unroll
        for (int j = 0; j < 8; j++) acc2[i][j] = 0ULL;

    // global-load roles
    const int ppB  = tid & 127;
    const int kkB0 = (tid >> 7) * 4;   // 0 or 4
    const int p    = p0 + ppB;
    const int y0p  = p / W;
    const int x0p  = p - y0p * W;
    const float* wrow = wgt + (size_t)tid * 2304;

    float4 av0, av1;
    float  bv[4];

    // ---- prefetch k0 = 0 ----
    av0 = *reinterpret_cast<const float4*>(wrow + 0);
    av1 = *reinterpret_cast<const float4*>(wrow + 4);
#pragma unroll
    for (int q = 0; q < 4; q++) {
        int k  = kkB0 + q;
        int ci = k / 9;
        int r  = k - ci * 9;
        int ky = r / 3;
        int kx = r - ky * 3;
        int yy = y0p + ky - 1;
        int xx = x0p + kx - 1;
        float v = 0.f;
        if ((unsigned)yy < (unsigned)H && (unsigned)xx < (unsigned)W)
            v = inN[(size_t)ci * HW + yy * W + xx];
        bv[q] = v;
    }
    {
        float wv0[4] = {av0.x, av0.y, av0.z, av0.w};
        float wv1[4] = {av1.x, av1.y, av1.z, av1.w};
#pragma unroll
        for (int q = 0; q < 4; q++) { As[0][q][tid] = wv0[q]; As[0][4 + q][tid] = wv1[q]; }
#pragma unroll
        for (int q = 0; q < 4; q++) Bs[0][kkB0 + q][ppB] = bv[q];
    }
    __syncthreads();

    int s = 0;
    for (int k0 = 0; k0 < 2304; k0 += 8) {
        const bool more = (k0 + 8) < 2304;
        if (more) {
            av0 = *reinterpret_cast<const float4*>(wrow + k0 + 8);
            av1 = *reinterpret_cast<const float4*>(wrow + k0 + 12);
#pragma unroll
            for (int q = 0; q < 4; q++) {
                int k  = k0 + 8 + kkB0 + q;
                int ci = k / 9;
                int r  = k - ci * 9;
                int ky = r / 3;
                int kx = r - ky * 3;
                int yy = y0p + ky - 1;
                int xx = x0p + kx - 1;
                float v = 0.f;
                if ((unsigned)yy < (unsigned)H && (unsigned)xx < (unsigned)W)
                    v = inN[(size_t)ci * HW + yy * W + xx];
                bv[q] = v;
            }
        }
        // ---- compute stage s ----
#pragma unroll
        for (int kk = 0; kk < 8; kk++) {
            unsigned long long a2[8];
#pragma unroll
            for (int q = 0; q < 4; q++) {
                ulonglong2 t = *reinterpret_cast<const ulonglong2*>(&As[s][kk][ty * 16 + q * 4]);
                a2[2 * q] = t.x; a2[2 * q + 1] = t.y;
            }
            float4 bq0 = *reinterpret_cast<const float4*>(&Bs[s][kk][tx * 4]);
            float4 bq1 = *reinterpret_cast<const float4*>(&Bs[s][kk][64 + tx * 4]);
            unsigned long long b2[8];
            b2[0] = dup2(bq0.x); b2[1] = dup2(bq0.y);
            b2[2] = dup2(bq0.z); b2[3] = dup2(bq0.w);
            b2[4] = dup2(bq1.x); b2[5] = dup2(bq1.y);
            b2[6] = dup2(bq1.z); b2[7] = dup2(bq1.w);
#pragma unroll
            for (int i = 0; i < 8; i++)
#pragma unroll
                for (int j = 0; j < 8; j++)
                    ffma2(acc2[i][j], a2[i], b2[j]);
        }
        if (more) {
            int d = s ^ 1;
            float wv0[4] = {av0.x, av0.y, av0.z, av0.w};
            float wv1[4] = {av1.x, av1.y, av1.z, av1.w};
#pragma unroll
            for (int q = 0; q < 4; q++) { As[d][q][tid] = wv0[q]; As[d][4 + q][tid] = wv1[q]; }
#pragma unroll
            for (int q = 0; q < 4; q++) Bs[d][kkB0 + q][ppB] = bv[q];
        }
        __syncthreads();
        s ^= 1;
    }

    // ---- epilogue: bias + relu, vectorized STG ----
#pragma unroll
    for (int i = 0; i < 8; i++) {
        int co = ty * 16 + 2 * i;
        float bb0 = bias[co], bb1 = bias[co + 1];
        float2 v[8];
#pragma unroll
        for (int j = 0; j < 8; j++) v[j] = unpack2(acc2[i][j]);
        float* o0 = tlev + ((size_t)(n * 256 + co)) * HW + p0;
        float* o1 = o0 + HW;
        float4 q00 = make_float4(fmaxf(v[0].x + bb0, 0.f), fmaxf(v[1].x + bb0, 0.f),
                                 fmaxf(v[2].x + bb0, 0.f), fmaxf(v[3].x + bb0, 0.f));
        float4 q01 = make_float4(fmaxf(v[4].x + bb0, 0.f), fmaxf(v[5].x + bb0, 0.f),
                                 fmaxf(v[6].x + bb0, 0.f), fmaxf(v[7].x + bb0, 0.f));
        float4 q10 = make_float4(fmaxf(v[0].y + bb1, 0.f), fmaxf(v[1].y + bb1, 0.f),
                                 fmaxf(v[2].y + bb1, 0.f), fmaxf(v[3].y + bb1, 0.f));
        float4 q11 = make_float4(fmaxf(v[4].y + bb1, 0.f), fmaxf(v[5].y + bb1, 0.f),
                                 fmaxf(v[6].y + bb1, 0.f), fmaxf(v[7].y + bb1, 0.f));
        *reinterpret_cast<float4*>(o0 + tx * 4)      = q00;
        *reinterpret_cast<float4*>(o0 + 64 + tx * 4) = q01;
        *reinterpret_cast<float4*>(o1 + tx * 4)      = q10;
        *reinterpret_cast<float4*>(o1 + 64 + tx * 4) = q11;
    }
}

// ------------------ fused all-level head + anchor decode + clip ------------------
__global__ __launch_bounds__(256) void head_all(
    const float* __restrict__ w_obj, const float* __restrict__ b_obj,
    const float* __restrict__ w_delta, const float* __restrict__ b_delta,
    AnchorP ap)
{
    int bx = blockIdx.x;
    int lvl, pt;
    if      (bx < 256) { lvl = 0; pt = bx; }
    else if (bx < 320) { lvl = 1; pt = bx - 256; }
    else if (bx < 336) { lvl = 2; pt = bx - 320; }
    else if (bx < 340) { lvl = 3; pt = bx - 336; }
    else               { lvl = 4; pt = bx - 340; }
    const int HW = c_HW[lvl];
    const int W  = c_H[lvl];
    const float stride = c_stride[lvl];
    const int n = blockIdx.y;
    const int p = pt * 256 + threadIdx.x;

    __shared__ float sw[15][256];
    for (int i = threadIdx.x; i < 15 * 256; i += 256) {
        int row = i >> 8, c = i & 255;
        sw[row][c] = (row < 3) ? w_obj[row * 256 + c] : w_delta[(row - 3) * 256 + c];
    }
    __syncthreads();
    if (p >= HW) return;

    float acc[15];
#pragma unroll
    for (int i = 0; i < 15; i++) acc[i] = 0.f;

    const float* tp = g_t + (size_t)512 * c_cumHW[lvl] + (size_t)n * 256 * HW + p;
    for (int c = 0; c < 256; c++) {
        float v = tp[(size_t)c * HW];
#pragma unroll
        for (int i = 0; i < 15; i++) acc[i] = fmaf(v, sw[i][c], acc[i]);
    }

    float gx = (float)(p % W) * stride;
    float gy = (float)(p / W) * stride;
#pragma unroll
    for (int a = 0; a < 3; a++) {
        float s  = acc[a] + b_obj[a];
        float dx = acc[3 + a * 4 + 0] + b_delta[a * 4 + 0];
        float dy = acc[3 + a * 4 + 1] + b_delta[a * 4 + 1];
        float dw = fminf(acc[3 + a * 4 + 2] + b_delta[a * 4 + 2], SCALE_CLAMP);
        float dh = fminf(acc[3 + a * 4 + 3] + b_delta[a * 4 + 3], SCALE_CLAMP);
        double CW = ap.cw[lvl * 3 + a], CH = ap.ch[lvl * 3 + a];
        float x0 = (float)((double)gx + CW);
        float x1 = (float)((double)gx - CW);
        float y0 = (float)((double)gy + CH);
        float y1 = (float)((double)gy - CH);
        float aw = x1 - x0, ah = y1 - y0;
        float acx = x0 + 0.5f * aw, acy = y0 + 0.5f * ah;
        float pcx = dx * aw + acx;
        float pcy = dy * ah + acy;
        float pw = expf(dw) * aw;
        float ph = expf(dh) * ah;
        float4 bx4;
        bx4.x = clip1024(pcx - 0.5f * pw);
        bx4.y = clip1024(pcy - 0.5f * ph);
        bx4.z = clip1024(pcx + 0.5f * pw);
        bx4.w = clip1024(pcy + 0.5f * ph);
        int idx = n * STOT + c_soff[lvl] + p * 3 + a;
        g_scores[idx] = s;
        g_boxes[idx]  = bx4;
    }
}

// ------------------ level-parallel radix-select (k-th largest) ------------------
__global__ void init_select() {
    int s = blockIdx.x;              // lvl*2+n
    if (threadIdx.x == 0) { g_prefix[s] = 0; g_krem[s] = (unsigned)c_k[s >> 1]; }
    g_hist[s * 256 + threadIdx.x] = 0;
}

__global__ void hist_kernel(int round) {
    __shared__ unsigned sh[256];
    int n = blockIdx.y, lvl = blockIdx.z;
    int s = lvl * 2 + n;
    sh[threadIdx.x] = 0;
    __syncthreads();
    unsigned pfx = g_prefix[s];
    int shift = 24 - 8 * round;
    unsigned maskhi = (round == 0) ? 0u : (0xFFFFFFFFu << (shift + 8));
    int L = c_L[lvl];
    const float* sc = g_scores + n * STOT + c_soff[lvl];
    for (int i = blockIdx.x * blockDim.x + threadIdx.x; i < L; i += gridDim.x * blockDim.x) {
        unsigned key = f2key(sc[i]);
        if (((key ^ pfx) & maskhi) == 0)
            atomicAdd(&sh[(key >> shift) & 255], 1u);
    }
    __syncthreads();
    if (sh[threadIdx.x]) atomicAdd(&g_hist[s * 256 + threadIdx.x], sh[threadIdx.x]);
}

__global__ void pick_kernel(int round) {
    int s = blockIdx.x;
    __shared__ unsigned h[256];
    h[threadIdx.x] = g_hist[s * 256 + threadIdx.x];
    __syncthreads();
    g_hist[s * 256 + threadIdx.x] = 0;
    if (threadIdx.x == 0) {
        int shift = 24 - 8 * round;
        unsigned kr = g_krem[s];
        unsigned cum = 0;
        int bin = 255;
        for (; bin > 0; bin--) {
            unsigned c = h[bin];
            if (cum + c >= kr) break;
            cum += c;
        }
        kr -= cum;
        unsigned pfx = g_prefix[s] | ((unsigned)bin << shift);
        g_prefix[s] = pfx;
        g_krem[s] = kr;
        if (round == 3) { g_kth[s] = pfx; g_needed[s] = kr; }
    }
}

// ------------------ compaction: exact top-k SET (ties -> lowest index) ------------------
__global__ __launch_bounds__(1024) void compact_kernel() {
    int n = blockIdx.x, lvl = blockIdx.y;
    int s = lvl * 2 + n;
    int L = c_L[lvl], k = c_k[lvl], lvl_off = lvl * 1000;
    unsigned kth = g_kth[s];
    int needed = (int)g_needed[s];
    int G = k - needed;
    const float* scp = g_scores + n * STOT + c_soff[lvl];
    const float4* bxp = g_boxes + n * STOT + c_soff[lvl];

    __shared__ unsigned wg[32], we[32];
    __shared__ int baseg, basee, totg, tote;
    if (threadIdx.x == 0) { baseg = 0; basee = 0; }
    __syncthreads();
    int lane = threadIdx.x & 31, w = threadIdx.x >> 5;

    for (int start = 0; start < L; start += 1024) {
        int i = start + threadIdx.x;
        bool gt = false, eq = false;
        float sc = 0.f;
        if (i < L) {
            sc = scp[i];
            unsigned key = f2key(sc);
            gt = key > kth;
            eq = (key == kth);
        }
        unsigned bg = __ballot_sync(0xffffffffu, gt);
        unsigned be = __ballot_sync(0xffffffffu, eq);
        if (lane == 0) { wg[w] = __popc(bg); we[w] = __popc(be); }
        __syncthreads();
        if (threadIdx.x < 32) {
            unsigned vg = wg[threadIdx.x], ve = we[threadIdx.x];
            unsigned ig = vg, ie = ve;
#pragma unroll
            for (int o = 1; o < 32; o <<= 1) {
                unsigned tg = __shfl_up_sync(0xffffffffu, ig, o);
                unsigned te = __shfl_up_sync(0xffffffffu, ie, o);
                if ((int)threadIdx.x >= o) { ig += tg; ie += te; }
            }
            wg[threadIdx.x] = ig - vg;
            we[threadIdx.x] = ie - ve;
            if (threadIdx.x == 31) { totg = (int)ig; tote = (int)ie; }
        }
        __syncthreads();
        if (gt) {
            int pos = baseg + (int)wg[w] + __popc(bg & ((1u << lane) - 1));
            g_cand_s[n * TCAND + lvl_off + pos] = sc;
            g_cand_b[n * TCAND + lvl_off + pos] = bxp[i];
        }
        if (eq) {
            int rank = basee + (int)we[w] + __popc(be & ((1u << lane) - 1));
            if (rank < needed) {
                int pos = G + rank;
                g_cand_s[n * TCAND + lvl_off + pos] = sc;
                g_cand_b[n * TCAND + lvl_off + pos] = bxp[i];
            }
        }
        __syncthreads();
        if (threadIdx.x == 0) { baseg += totg; basee += tote; }
        __syncthreads();
    }
}

// ------------------ per-image bitonic sort (score desc, idx asc) ------------------
__global__ __launch_bounds__(1024) void sort_kernel() {
    extern __shared__ unsigned long long keys[];
    int n = blockIdx.x;
    for (int i = threadIdx.x; i < 8192; i += 1024) {
        unsigned long long kk;
        if (i < TCAND) {
            unsigned sk = f2key(g_cand_s[n * TCAND + i]);
            kk = ((unsigned long long)(~sk) << 32) | (unsigned)i;
        } else kk = ~0ULL;
        keys[i] = kk;
    }
    for (int k = 2; k <= 8192; k <<= 1) {
        for (int j = k >> 1; j > 0; j >>= 1) {
            __syncthreads();
            for (int i = threadIdx.x; i < 8192; i += 1024) {
                int ixj = i ^ j;
                if (ixj > i) {
                    unsigned long long a = keys[i], b = keys[ixj];
                    bool up = ((i & k) == 0);
                    if ((a > b) == up) { keys[i] = b; keys[ixj] = a; }
                }
            }
        }
    }
    __syncthreads();
    for (int i = threadIdx.x; i < TCAND; i += 1024) {
        int j = (int)(unsigned)(keys[i] & 0xffffffffu);
        float s = g_cand_s[n * TCAND + j];
        float4 b = g_cand_b[n * TCAND + j];
        int lvl = (j < 4000) ? (j / 1000) : 4;
        float off = (float)lvl * 1025.0f;
        float4 ob = make_float4(b.x + off, b.y + off, b.z + off, b.w + off);
        g_sorted_s[n * TCAND + i] = s;
        g_sorted_b[n * TCAND + i] = b;
        g_sorted_ob[n * TCAND + i] = ob;
        bool valid = (b.z - b.x > 0.f) && (b.w - b.y > 0.f);
        unsigned bal = __ballot_sync(0xffffffffu, valid);
        if ((threadIdx.x & 31) == 0) g_validw[n * NWORDS + (i >> 5)] = bal;
    }
}

// ------------------ IoU suppression bit-matrix (j > i only) ------------------
__global__ __launch_bounds__(256) void iou_kernel() {
    int n = blockIdx.z;
    int i = blockIdx.y;
    int j = blockIdx.x * 256 + threadIdx.x;
    float4 bi = g_sorted_ob[n * TCAND + i];
    bool sup = false;
    if (j < TCAND && j > i) {
        float4 bj = g_sorted_ob[n * TCAND + j];
        float areai = (bi.z - bi.x) * (bi.w - bi.y);
        float areaj = (bj.z - bj.x) * (bj.w - bj.y);
        float ltx = fmaxf(bi.x, bj.x), lty = fmaxf(bi.y, bj.y);
        float rbx = fminf(bi.z, bj.z), rby = fminf(bi.w, bj.w);
        float iw = fmaxf(rbx - ltx, 0.f), ih = fmaxf(rby - lty, 0.f);
        float inter = iw * ih;
        float uni = areai + areaj - inter;
        float iou = (uni > 0.f) ? (inter / uni) : 0.f;
        sup = iou > 0.7f;
    }
    unsigned bal = __ballot_sync(0xffffffffu, sup);
    if ((threadIdx.x & 31) == 0) {
        int wq = j >> 5;
        if (wq < NWORDS) g_mask[((size_t)n * TCAND + i) * NWORDS + wq] = bal;
    }
}

// ------------------ sequential greedy scan + ordered emission (1 warp / image) ------------------
__global__ void nms_scan(float* __restrict__ out) {
    int n = blockIdx.x;
    int lane = threadIdx.x;
    unsigned keep[5];
#pragma unroll
    for (int q = 0; q < 5; q++) {
        int w = lane * 5 + q;
        keep[q] = (w < NWORDS) ? 0xFFFFFFFFu : 0u;
    }
    const unsigned* mask = g_mask + (size_t)n * TCAND * NWORDS;
    const int NCH = TCAND / 8;
    unsigned cur[8][5], nxt[8][5];
#pragma unroll
    for (int t = 0; t < 8; t++)
#pragma unroll
        for (int q = 0; q < 5; q++) {
            int w = lane * 5 + q;
            cur[t][q] = (w < NWORDS) ? mask[(size_t)t * NWORDS + w] : 0u;
        }
    for (int c = 0; c < NCH; c++) {
        if (c + 1 < NCH) {
            int base = (c + 1) * 8;
#pragma unroll
            for (int t = 0; t < 8; t++)
#pragma unroll
                for (int q = 0; q < 5; q++) {
                    int w = lane * 5 + q;
                    nxt[t][q] = (w < NWORDS) ? mask[(size_t)(base + t) * NWORDS + w] : 0u;
                }
        }
#pragma unroll
        for (int t = 0; t < 8; t++) {
            int i = c * 8 + t;
            int wi = i >> 5;
            int owner = wi / 5;
            int qi = wi - owner * 5;
            unsigned kw;
            switch (qi) {
                case 0: kw = keep[0]; break;
                case 1: kw = keep[1]; break;
                case 2: kw = keep[2]; break;
                case 3: kw = keep[3]; break;
                default: kw = keep[4]; break;
            }
            unsigned word = __shfl_sync(0xffffffffu, kw, owner);
            if ((word >> (i & 31)) & 1u) {
#pragma unroll
                for (int q = 0; q < 5; q++) keep[q] &= ~cur[t][q];
            }
        }
#pragma unroll
        for (int t = 0; t < 8; t++)
#pragma unroll
            for (int q = 0; q < 5; q++) cur[t][q] = nxt[t][q];
    }
#pragma unroll
    for (int q = 0; q < 5; q++) {
        int w = lane * 5 + q;
        if (w < NWORDS) keep[q] &= g_validw[n * NWORDS + w];
    }
    int mycnt = 0;
#pragma unroll
    for (int q = 0; q < 5; q++) mycnt += __popc(keep[q]);
    int incl = mycnt;
#pragma unroll
    for (int o = 1; o < 32; o <<= 1) {
        int t = __shfl_up_sync(0xffffffffu, incl, o);
        if (lane >= o) incl += t;
    }
    int nk = __shfl_sync(0xffffffffu, incl, 31);
    int run = incl - mycnt;
    float ninf = __int_as_float((int)0xff800000u);
    float* outS = out + 8000;
#pragma unroll
    for (int q = 0; q < 5; q++) {
        int w = lane * 5 + q;
        if (w >= NWORDS) continue;
        unsigned kwv = keep[q];
        for (int b = 0; b < 32; b++) {
            int i = w * 32 + b;
            int ones_before = run + __popc(kwv & ((1u << b) - 1));
            bool kept = (kwv >> b) & 1u;
            int pos = kept ? ones_before : (nk + (i - ones_before));
            if (pos < 1000) {
                float4 bx = g_sorted_b[n * TCAND + i];
                float* ob = out + ((size_t)n * 1000 + pos) * 4;
                ob[0] = bx.x; ob[1] = bx.y; ob[2] = bx.z; ob[3] = bx.w;
                outS[n * 1000 + pos] = kept ? g_sorted_s[n * TCAND + i] : ninf;
            }
        }
        run += __popc(kwv);
    }
}

// ------------------ launch ------------------
extern "C" void kernel_launch(void* const* d_in, const int* in_sizes, int n_in,
                              void* d_out, int out_size) {
    (void)in_sizes; (void)n_in; (void)out_size;
    Feats feats;
    for (int i = 0; i < 5; i++) feats.p[i] = (const float*)d_in[i];
    const float* w_conv  = (const float*)d_in[5];
    const float* b_conv  = (const float*)d_in[6];
    const float* w_obj   = (const float*)d_in[7];
    const float* b_obj   = (const float*)d_in[8];
    const float* w_delta = (const float*)d_in[9];
    const float* b_delta = (const float*)d_in[10];

    static const double sizesT[5] = {32.0, 64.0, 128.0, 256.0, 512.0};
    static const double ratios[3] = {0.5, 1.0, 2.0};
    AnchorP ap;
    for (int l = 0; l < 5; l++) {
        double area = sizesT[l] * sizesT[l];
        for (int a = 0; a < 3; a++) {
            double w = sqrt(area / ratios[a]);
            double h = w * ratios[a];
            ap.cw[l * 3 + a] = -w / 2.0;
            ap.ch[l * 3 + a] = -h / 2.0;
        }
    }

    conv3x3_relu_all<<<dim3(682, NIMG), 256>>>(feats, w_conv, b_conv);
    head_all<<<dim3(341, NIMG), 256>>>(w_obj, b_obj, w_delta, b_delta, ap);

    init_select<<<10, 256>>>();
    for (int r = 0; r < 4; r++) {
        hist_kernel<<<dim3(32, NIMG, 5), 256>>>(r);
        pick_kernel<<<10, 256>>>(r);
    }
    compact_kernel<<<dim3(NIMG, 5), 1024>>>();

    cudaFuncSetAttribute(sort_kernel, cudaFuncAttributeMaxDynamicSharedMemorySize, 65536);
    sort_kernel<<<NIMG, 1024, 65536>>>();
    iou_kernel<<<dim3((TCAND + 255) / 256, TCAND, NIMG), 256>>>();
    nms_scan<<<NIMG, 32>>>((float*)d_out);
}

// round 6
// speedup vs baseline: 1.4010x; 1.0052x over previous
#include <cuda_runtime.h>
#include <math.h>
#include <stdint.h>

#define NIMG   2
#define TCAND  4768           // 4*1000 + 768
#define NWORDS 149            // 4768/32 exactly
#define STOT   261888         // total anchors per image (sum HW*3)
#define SCALE_CLAMP 4.135166556742356f
#define NTILES 1364           // 682 pixel tiles * 2 images
#define PERSIST_CTAS 152

// ------------------ static device scratch ------------------
__device__ float    g_t[44695552];            // 2*256*87296 conv outputs, all levels
__device__ float    g_scores[NIMG * STOT];
__device__ float4   g_boxes [NIMG * STOT];
__device__ unsigned g_hist[10 * 256];         // [lvl*2+n][256]
__device__ unsigned g_prefix[10];
__device__ unsigned g_krem[10];
__device__ unsigned g_kth[10];
__device__ unsigned g_needed[10];
__device__ float    g_cand_s[NIMG * TCAND];
__device__ float4   g_cand_b[NIMG * TCAND];
__device__ float    g_sorted_s[NIMG * TCAND];
__device__ float4   g_sorted_b[NIMG * TCAND];
__device__ float4   g_sorted_ob[NIMG * TCAND];
__device__ unsigned g_validw[NIMG * NWORDS];
__device__ unsigned g_mask[NIMG * TCAND * NWORDS];

// ------------------ level tables ------------------
__constant__ int   c_H[5]      = {256, 128, 64, 32, 16};
__constant__ int   c_HW[5]     = {65536, 16384, 4096, 1024, 256};
__constant__ int   c_cumHW[5]  = {0, 65536, 81920, 86016, 87040};
__constant__ float c_stride[5] = {4.f, 8.f, 16.f, 32.f, 64.f};
__constant__ int   c_soff[5]   = {0, 196608, 245760, 258048, 261120};
__constant__ int   c_L[5]      = {196608, 49152, 12288, 3072, 768};
__constant__ int   c_k[5]      = {1000, 1000, 1000, 1000, 768};

struct Feats { const float* p[5]; };
struct AnchorP { double cw[15]; double ch[15]; };   // [lvl*3+a]

// ------------------ helpers ------------------
__device__ __forceinline__ unsigned f2key(float f) {
    unsigned u = __float_as_uint(f);
    return (u & 0x80000000u) ? ~u : (u | 0x80000000u);
}
__device__ __forceinline__ float clip1024(float v) { return fminf(fmaxf(v, 0.f), 1024.f); }

__device__ __forceinline__ void ffma2(unsigned long long& d, unsigned long long a, unsigned long long b) {
    asm("fma.rn.f32x2 %0, %1, %2, %0;" : "+l"(d) : "l"(a), "l"(b));
}
__device__ __forceinline__ unsigned long long dup2(float x) {
    unsigned long long r;
    asm("mov.b64 %0, {%1, %1};" : "=l"(r) : "f"(x));
    return r;
}
__device__ __forceinline__ float2 unpack2(unsigned long long v) {
    float2 r;
    asm("mov.b64 {%0, %1}, %2;" : "=f"(r.x), "=f"(r.y) : "l"(v));
    return r;
}

// ------------------ persistent FFMA2 implicit-GEMM conv3x3 SAME + bias + relu ------------------
// block tile: 256 co x 128 px, thread tile 16 co (8 f32x2 pairs) x 8 px.
// persistent grid of PERSIST_CTAS; static stride over NTILES tiles.
__global__ __launch_bounds__(256, 1) void conv3x3_relu_all(
    Feats feats, const float* __restrict__ wgt, const float* __restrict__ bias)
{
    __shared__ __align__(16) float As[2][8][256];   // [stage][kk][co]
    __shared__ __align__(16) float Bs[2][8][128];   // [stage][kk][px]

    const int tid = threadIdx.x;
    const int tx = tid & 15, ty = tid >> 4;
    const int ppB  = tid & 127;
    const int kkB0 = (tid >> 7) * 4;   // 0 or 4
    const float* wrow = wgt + (size_t)tid * 2304;

    for (int t = blockIdx.x; t < NTILES; t += gridDim.x) {
        const int n  = t / 682;
        int bx = t - n * 682;
        int lvl, pt;
        if      (bx < 512) { lvl = 0; pt = bx; }
        else if (bx < 640) { lvl = 1; pt = bx - 512; }
        else if (bx < 672) { lvl = 2; pt = bx - 640; }
        else if (bx < 680) { lvl = 3; pt = bx - 672; }
        else               { lvl = 4; pt = bx - 680; }
        const int H  = c_H[lvl];
        const int W  = H;
        const int HW = c_HW[lvl];
        const int p0 = pt * 128;
        const float* inN = feats.p[lvl] + (size_t)n * 256 * HW;
        float* tlev = g_t + (size_t)512 * c_cumHW[lvl];

        unsigned long long acc2[8][8];
#pragma unroll
        for (int i = 0; i < 8; i++)
#pragma unroll
            for (int j = 0; j < 8; j++) acc2[i][j] = 0ULL;

        const int p   = p0 + ppB;
        const int y0p = p / W;
        const int x0p = p - y0p * W;

        float4 av0, av1;
        float  bv[4];

        // ---- prefetch k0 = 0 ----
        av0 = *reinterpret_cast<const float4*>(wrow + 0);
        av1 = *reinterpret_cast<const float4*>(wrow + 4);
#pragma unroll
        for (int q = 0; q < 4; q++) {
            int k  = kkB0 + q;
            int ci = k / 9;
            int r  = k - ci * 9;
            int ky = r / 3;
            int kx = r - ky * 3;
            int yy = y0p + ky - 1;
            int xx = x0p + kx - 1;
            float v = 0.f;
            if ((unsigned)yy < (unsigned)H && (unsigned)xx < (unsigned)W)
                v = inN[(size_t)ci * HW + yy * W + xx];
            bv[q] = v;
        }
        {
            float wv0[4] = {av0.x, av0.y, av0.z, av0.w};
            float wv1[4] = {av1.x, av1.y, av1.z, av1.w};
#pragma unroll
            for (int q = 0; q < 4; q++) { As[0][q][tid] = wv0[q]; As[0][4 + q][tid] = wv1[q]; }
#pragma unroll
            for (int q = 0; q < 4; q++) Bs[0][kkB0 + q][ppB] = bv[q];
        }
        __syncthreads();

        int s = 0;
        for (int k0 = 0; k0 < 2304; k0 += 8) {
            const bool more = (k0 + 8) < 2304;
            if (more) {
                av0 = *reinterpret_cast<const float4*>(wrow + k0 + 8);
                av1 = *reinterpret_cast<const float4*>(wrow + k0 + 12);
#pragma unroll
                for (int q = 0; q < 4; q++) {
                    int k  = k0 + 8 + kkB0 + q;
                    int ci = k / 9;
                    int r  = k - ci * 9;
                    int ky = r / 3;
                    int kx = r - ky * 3;
                    int yy = y0p + ky - 1;
                    int xx = x0p + kx - 1;
                    float v = 0.f;
                    if ((unsigned)yy < (unsigned)H && (unsigned)xx < (unsigned)W)
                        v = inN[(size_t)ci * HW + yy * W + xx];
                    bv[q] = v;
                }
            }
            // ---- compute stage s ----
#pragma unroll
            for (int kk = 0; kk < 8; kk++) {
                unsigned long long a2[8];
#pragma unroll
                for (int q = 0; q < 4; q++) {
                    ulonglong2 tt = *reinterpret_cast<const ulonglong2*>(&As[s][kk][ty * 16 + q * 4]);
                    a2[2 * q] = tt.x; a2[2 * q + 1] = tt.y;
                }
                float4 bq0 = *reinterpret_cast<const float4*>(&Bs[s][kk][tx * 4]);
                float4 bq1 = *reinterpret_cast<const float4*>(&Bs[s][kk][64 + tx * 4]);
                unsigned long long b2[8];
                b2[0] = dup2(bq0.x); b2[1] = dup2(bq0.y);
                b2[2] = dup2(bq0.z); b2[3] = dup2(bq0.w);
                b2[4] = dup2(bq1.x); b2[5] = dup2(bq1.y);
                b2[6] = dup2(bq1.z); b2[7] = dup2(bq1.w);
#pragma unroll
                for (int i = 0; i < 8; i++)
#pragma unroll
                    for (int j = 0; j < 8; j++)
                        ffma2(acc2[i][j], a2[i], b2[j]);
            }
            if (more) {
                int d = s ^ 1;
                float wv0[4] = {av0.x, av0.y, av0.z, av0.w};
                float wv1[4] = {av1.x, av1.y, av1.z, av1.w};
#pragma unroll
                for (int q = 0; q < 4; q++) { As[d][q][tid] = wv0[q]; As[d][4 + q][tid] = wv1[q]; }
#pragma unroll
                for (int q = 0; q < 4; q++) Bs[d][kkB0 + q][ppB] = bv[q];
            }
            __syncthreads();
            s ^= 1;
        }

        // ---- epilogue: bias + relu, vectorized STG ----
#pragma unroll
        for (int i = 0; i < 8; i++) {
            int co = ty * 16 + 2 * i;
            float bb0 = bias[co], bb1 = bias[co + 1];
            float2 v[8];
#pragma unroll
            for (int j = 0; j < 8; j++) v[j] = unpack2(acc2[i][j]);
            float* o0 = tlev + ((size_t)(n * 256 + co)) * HW + p0;
            float* o1 = o0 + HW;
            float4 q00 = make_float4(fmaxf(v[0].x + bb0, 0.f), fmaxf(v[1].x + bb0, 0.f),
                                     fmaxf(v[2].x + bb0, 0.f), fmaxf(v[3].x + bb0, 0.f));
            float4 q01 = make_float4(fmaxf(v[4].x + bb0, 0.f), fmaxf(v[5].x + bb0, 0.f),
                                     fmaxf(v[6].x + bb0, 0.f), fmaxf(v[7].x + bb0, 0.f));
            float4 q10 = make_float4(fmaxf(v[0].y + bb1, 0.f), fmaxf(v[1].y + bb1, 0.f),
                                     fmaxf(v[2].y + bb1, 0.f), fmaxf(v[3].y + bb1, 0.f));
            float4 q11 = make_float4(fmaxf(v[4].y + bb1, 0.f), fmaxf(v[5].y + bb1, 0.f),
                                     fmaxf(v[6].y + bb1, 0.f), fmaxf(v[7].y + bb1, 0.f));
            *reinterpret_cast<float4*>(o0 + tx * 4)      = q00;
            *reinterpret_cast<float4*>(o0 + 64 + tx * 4) = q01;
            *reinterpret_cast<float4*>(o1 + tx * 4)      = q10;
            *reinterpret_cast<float4*>(o1 + 64 + tx * 4) = q11;
        }
        __syncthreads();   // smem safe for next tile's prefetch
    }
}

// ------------------ fused all-level head + anchor decode + clip ------------------
__global__ __launch_bounds__(256) void head_all(
    const float* __restrict__ w_obj, const float* __restrict__ b_obj,
    const float* __restrict__ w_delta, const float* __restrict__ b_delta,
    AnchorP ap)
{
    int bx = blockIdx.x;
    int lvl, pt;
    if      (bx < 256) { lvl = 0; pt = bx; }
    else if (bx < 320) { lvl = 1; pt = bx - 256; }
    else if (bx < 336) { lvl = 2; pt = bx - 320; }
    else if (bx < 340) { lvl = 3; pt = bx - 336; }
    else               { lvl = 4; pt = bx - 340; }
    const int HW = c_HW[lvl];
    const int W  = c_H[lvl];
    const float stride = c_stride[lvl];
    const int n = blockIdx.y;
    const int p = pt * 256 + threadIdx.x;

    __shared__ float sw[15][256];
    for (int i = threadIdx.x; i < 15 * 256; i += 256) {
        int row = i >> 8, c = i & 255;
        sw[row][c] = (row < 3) ? w_obj[row * 256 + c] : w_delta[(row - 3) * 256 + c];
    }
    __syncthreads();
    if (p >= HW) return;

    float acc[15];
#pragma unroll
    for (int i = 0; i < 15; i++) acc[i] = 0.f;

    const float* tp = g_t + (size_t)512 * c_cumHW[lvl] + (size_t)n * 256 * HW + p;
    for (int c = 0; c < 256; c++) {
        float v = tp[(size_t)c * HW];
#pragma unroll
        for (int i = 0; i < 15; i++) acc[i] = fmaf(v, sw[i][c], acc[i]);
    }

    float gx = (float)(p % W) * stride;
    float gy = (float)(p / W) * stride;
#pragma unroll
    for (int a = 0; a < 3; a++) {
        float s  = acc[a] + b_obj[a];
        float dx = acc[3 + a * 4 + 0] + b_delta[a * 4 + 0];
        float dy = acc[3 + a * 4 + 1] + b_delta[a * 4 + 1];
        float dw = fminf(acc[3 + a * 4 + 2] + b_delta[a * 4 + 2], SCALE_CLAMP);
        float dh = fminf(acc[3 + a * 4 + 3] + b_delta[a * 4 + 3], SCALE_CLAMP);
        double CW = ap.cw[lvl * 3 + a], CH = ap.ch[lvl * 3 + a];
        float x0 = (float)((double)gx + CW);
        float x1 = (float)((double)gx - CW);
        float y0 = (float)((double)gy + CH);
        float y1 = (float)((double)gy - CH);
        float aw = x1 - x0, ah = y1 - y0;
        float acx = x0 + 0.5f * aw, acy = y0 + 0.5f * ah;
        float pcx = dx * aw + acx;
        float pcy = dy * ah + acy;
        float pw = expf(dw) * aw;
        float ph = expf(dh) * ah;
        float4 bx4;
        bx4.x = clip1024(pcx - 0.5f * pw);
        bx4.y = clip1024(pcy - 0.5f * ph);
        bx4.z = clip1024(pcx + 0.5f * pw);
        bx4.w = clip1024(pcy + 0.5f * ph);
        int idx = n * STOT + c_soff[lvl] + p * 3 + a;
        g_scores[idx] = s;
        g_boxes[idx]  = bx4;
    }
}

// ------------------ level-parallel radix-select ------------------
__global__ void init_select() {
    int s = blockIdx.x;              // lvl*2+n
    if (threadIdx.x == 0) { g_prefix[s] = 0; g_krem[s] = (unsigned)c_k[s >> 1]; }
    g_hist[s * 256 + threadIdx.x] = 0;
}

__global__ void hist_kernel(int round) {
    __shared__ unsigned sh[256];
    int n = blockIdx.y, lvl = blockIdx.z;
    int s = lvl * 2 + n;
    sh[threadIdx.x] = 0;
    __syncthreads();
    unsigned pfx = g_prefix[s];
    int shift = 24 - 8 * round;
    unsigned maskhi = (round == 0) ? 0u : (0xFFFFFFFFu << (shift + 8));
    int L = c_L[lvl];
    const float* sc = g_scores + n * STOT + c_soff[lvl];
    for (int i = blockIdx.x * blockDim.x + threadIdx.x; i < L; i += gridDim.x * blockDim.x) {
        unsigned key = f2key(sc[i]);
        if (((key ^ pfx) & maskhi) == 0)
            atomicAdd(&sh[(key >> shift) & 255], 1u);
    }
    __syncthreads();
    if (sh[threadIdx.x]) atomicAdd(&g_hist[s * 256 + threadIdx.x], sh[threadIdx.x]);
}

__global__ void pick_kernel(int round) {
    int s = blockIdx.x;
    __shared__ unsigned h[256];
    h[threadIdx.x] = g_hist[s * 256 + threadIdx.x];
    __syncthreads();
    g_hist[s * 256 + threadIdx.x] = 0;
    if (threadIdx.x == 0) {
        int shift = 24 - 8 * round;
        unsigned kr = g_krem[s];
        unsigned cum = 0;
        int bin = 255;
        for (; bin > 0; bin--) {
            unsigned c = h[bin];
            if (cum + c >= kr) break;
            cum += c;
        }
        kr -= cum;
        unsigned pfx = g_prefix[s] | ((unsigned)bin << shift);
        g_prefix[s] = pfx;
        g_krem[s] = kr;
        if (round == 3) { g_kth[s] = pfx; g_needed[s] = kr; }
    }
}

// ------------------ compaction: exact top-k SET (ties -> lowest index) ------------------
__global__ __launch_bounds__(1024) void compact_kernel() {
    int n = blockIdx.x, lvl = blockIdx.y;
    int s = lvl * 2 + n;
    int L = c_L[lvl], k = c_k[lvl], lvl_off = lvl * 1000;
    unsigned kth = g_kth[s];
    int needed = (int)g_needed[s];
    int G = k - needed;
    const float* scp = g_scores + n * STOT + c_soff[lvl];
    const float4* bxp = g_boxes + n * STOT + c_soff[lvl];

    __shared__ unsigned wg[32], we[32];
    __shared__ int baseg, basee, totg, tote;
    if (threadIdx.x == 0) { baseg = 0; basee = 0; }
    __syncthreads();
    int lane = threadIdx.x & 31, w = threadIdx.x >> 5;

    for (int start = 0; start < L; start += 1024) {
        int i = start + threadIdx.x;
        bool gt = false, eq = false;
        float sc = 0.f;
        if (i < L) {
            sc = scp[i];
            unsigned key = f2key(sc);
            gt = key > kth;
            eq = (key == kth);
        }
        unsigned bg = __ballot_sync(0xffffffffu, gt);
        unsigned be = __ballot_sync(0xffffffffu, eq);
        if (lane == 0) { wg[w] = __popc(bg); we[w] = __popc(be); }
        __syncthreads();
        if (threadIdx.x < 32) {
            unsigned vg = wg[threadIdx.x], ve = we[threadIdx.x];
            unsigned ig = vg, ie = ve;
#pragma unroll
            for (int o = 1; o < 32; o <<= 1) {
                unsigned tg = __shfl_up_sync(0xffffffffu, ig, o);
                unsigned te = __shfl_up_sync(0xffffffffu, ie, o);
                if ((int)threadIdx.x >= o) { ig += tg; ie += te; }
            }
            wg[threadIdx.x] = ig - vg;
            we[threadIdx.x] = ie - ve;
            if (threadIdx.x == 31) { totg = (int)ig; tote = (int)ie; }
        }
        __syncthreads();
        if (gt) {
            int pos = baseg + (int)wg[w] + __popc(bg & ((1u << lane) - 1));
            g_cand_s[n * TCAND + lvl_off + pos] = sc;
            g_cand_b[n * TCAND + lvl_off + pos] = bxp[i];
        }
        if (eq) {
            int rank = basee + (int)we[w] + __popc(be & ((1u << lane) - 1));
            if (rank < needed) {
                int pos = G + rank;
                g_cand_s[n * TCAND + lvl_off + pos] = sc;
                g_cand_b[n * TCAND + lvl_off + pos] = bxp[i];
            }
        }
        __syncthreads();
        if (threadIdx.x == 0) { baseg += totg; basee += tote; }
        __syncthreads();
    }
}

// ------------------ per-image bitonic sort (score desc, idx asc) ------------------
__global__ __launch_bounds__(1024) void sort_kernel() {
    extern __shared__ unsigned long long keys[];
    int n = blockIdx.x;
    for (int i = threadIdx.x; i < 8192; i += 1024) {
        unsigned long long kk;
        if (i < TCAND) {
            unsigned sk = f2key(g_cand_s[n * TCAND + i]);
            kk = ((unsigned long long)(~sk) << 32) | (unsigned)i;
        } else kk = ~0ULL;
        keys[i] = kk;
    }
    for (int k = 2; k <= 8192; k <<= 1) {
        for (int j = k >> 1; j > 0; j >>= 1) {
            __syncthreads();
            for (int i = threadIdx.x; i < 8192; i += 1024) {
                int ixj = i ^ j;
                if (ixj > i) {
                    unsigned long long a = keys[i], b = keys[ixj];
                    bool up = ((i & k) == 0);
                    if ((a > b) == up) { keys[i] = b; keys[ixj] = a; }
                }
            }
        }
    }
    __syncthreads();
    for (int i = threadIdx.x; i < TCAND; i += 1024) {
        int j = (int)(unsigned)(keys[i] & 0xffffffffu);
        float s = g_cand_s[n * TCAND + j];
        float4 b = g_cand_b[n * TCAND + j];
        int lvl = (j < 4000) ? (j / 1000) : 4;
        float off = (float)lvl * 1025.0f;
        float4 ob = make_float4(b.x + off, b.y + off, b.z + off, b.w + off);
        g_sorted_s[n * TCAND + i] = s;
        g_sorted_b[n * TCAND + i] = b;
        g_sorted_ob[n * TCAND + i] = ob;
        bool valid = (b.z - b.x > 0.f) && (b.w - b.y > 0.f);
        unsigned bal = __ballot_sync(0xffffffffu, valid);
        if ((threadIdx.x & 31) == 0) g_validw[n * NWORDS + (i >> 5)] = bal;
    }
}

// ------------------ IoU suppression bit-matrix (i-tiled, j > i only) ------------------
// grid: (jblocks=19, iblocks=149, NIMG), block 256. 32 i-rows per block, bi in smem.
__global__ __launch_bounds__(256) void iou_kernel() {
    __shared__ float4 sbi[32];
    int n  = blockIdx.z;
    int i0 = blockIdx.y * 32;
    int j  = blockIdx.x * 256 + threadIdx.x;

    if (threadIdx.x < 32) {
        int i = i0 + threadIdx.x;
        sbi[threadIdx.x] = (i < TCAND) ? g_sorted_ob[n * TCAND + i]
                                       : make_float4(0.f, 0.f, 0.f, 0.f);
    }
    __syncthreads();

    float4 bj = make_float4(0.f, 0.f, 0.f, 0.f);
    if (j < TCAND) bj = g_sorted_ob[n * TCAND + j];
    float areaj = (bj.z - bj.x) * (bj.w - bj.y);
    int wq = j >> 5;

#pragma unroll 4
    for (int ii = 0; ii < 32; ii++) {
        int i = i0 + ii;
        if (i >= TCAND) break;
        float4 bi = sbi[ii];
        bool sup = false;
        if (j < TCAND && j > i) {
            float areai = (bi.z - bi.x) * (bi.w - bi.y);
            float ltx = fmaxf(bi.x, bj.x), lty = fmaxf(bi.y, bj.y);
            float rbx = fminf(bi.z, bj.z), rby = fminf(bi.w, bj.w);
            float iw = fmaxf(rbx - ltx, 0.f), ih = fmaxf(rby - lty, 0.f);
            float inter = iw * ih;
            float uni = areai + areaj - inter;
            float iou = (uni > 0.f) ? (inter / uni) : 0.f;
            sup = iou > 0.7f;
        }
        unsigned bal = __ballot_sync(0xffffffffu, sup);
        if ((threadIdx.x & 31) == 0 && wq < NWORDS)
            g_mask[((size_t)n * TCAND + i) * NWORDS + wq] = bal;
    }
}

// ------------------ sequential greedy scan + ordered emission (1 warp / image) ------------------
__global__ void nms_scan(float* __restrict__ out) {
    int n = blockIdx.x;
    int lane = threadIdx.x;
    unsigned keep[5];
#pragma unroll
    for (int q = 0; q < 5; q++) {
        int w = lane * 5 + q;
        keep[q] = (w < NWORDS) ? 0xFFFFFFFFu : 0u;
    }
    const unsigned* mask = g_mask + (size_t)n * TCAND * NWORDS;
    const int NCH = TCAND / 8;
    unsigned cur[8][5], nxt[8][5];
#pragma unroll
    for (int t = 0; t < 8; t++)
#pragma unroll
        for (int q = 0; q < 5; q++) {
            int w = lane * 5 + q;
            cur[t][q] = (w < NWORDS) ? mask[(size_t)t * NWORDS + w] : 0u;
        }
    for (int c = 0; c < NCH; c++) {
        if (c + 1 < NCH) {
            int base = (c + 1) * 8;
#pragma unroll
            for (int t = 0; t < 8; t++)
#pragma unroll
                for (int q = 0; q < 5; q++) {
                    int w = lane * 5 + q;
                    nxt[t][q] = (w < NWORDS) ? mask[(size_t)(base + t) * NWORDS + w] : 0u;
                }
        }
#pragma unroll
        for (int t = 0; t < 8; t++) {
            int i = c * 8 + t;
            int wi = i >> 5;
            int owner = wi / 5;
            int qi = wi - owner * 5;
            unsigned kw;
            switch (qi) {
                case 0: kw = keep[0]; break;
                case 1: kw = keep[1]; break;
                case 2: kw = keep[2]; break;
                case 3: kw = keep[3]; break;
                default: kw = keep[4]; break;
            }
            unsigned word = __shfl_sync(0xffffffffu, kw, owner);
            if ((word >> (i & 31)) & 1u) {
#pragma unroll
                for (int q = 0; q < 5; q++) keep[q] &= ~cur[t][q];
            }
        }
#pragma unroll
        for (int t = 0; t < 8; t++)
#pragma unroll
            for (int q = 0; q < 5; q++) cur[t][q] = nxt[t][q];
    }
#pragma unroll
    for (int q = 0; q < 5; q++) {
        int w = lane * 5 + q;
        if (w < NWORDS) keep[q] &= g_validw[n * NWORDS + w];
    }
    int mycnt = 0;
#pragma unroll
    for (int q = 0; q < 5; q++) mycnt += __popc(keep[q]);
    int incl = mycnt;
#pragma unroll
    for (int o = 1; o < 32; o <<= 1) {
        int t = __shfl_up_sync(0xffffffffu, incl, o);
        if (lane >= o) incl += t;
    }
    int nk = __shfl_sync(0xffffffffu, incl, 31);
    int run = incl - mycnt;
    float ninf = __int_as_float((int)0xff800000u);
    float* outS = out + 8000;
#pragma unroll
    for (int q = 0; q < 5; q++) {
        int w = lane * 5 + q;
        if (w >= NWORDS) continue;
        unsigned kwv = keep[q];
        for (int b = 0; b < 32; b++) {
            int i = w * 32 + b;
            int ones_before = run + __popc(kwv & ((1u << b) - 1));
            bool kept = (kwv >> b) & 1u;
            int pos = kept ? ones_before : (nk + (i - ones_before));
            if (pos < 1000) {
                float4 bx = g_sorted_b[n * TCAND + i];
                float* ob = out + ((size_t)n * 1000 + pos) * 4;
                ob[0] = bx.x; ob[1] = bx.y; ob[2] = bx.z; ob[3] = bx.w;
                outS[n * 1000 + pos] = kept ? g_sorted_s[n * TCAND + i] : ninf;
            }
        }
        run += __popc(kwv);
    }
}

// ------------------ launch ------------------
extern "C" void kernel_launch(void* const* d_in, const int* in_sizes, int n_in,
                              void* d_out, int out_size) {
    (void)in_sizes; (void)n_in; (void)out_size;
    Feats feats;
    for (int i = 0; i < 5; i++) feats.p[i] = (const float*)d_in[i];
    const float* w_conv  = (const float*)d_in[5];
    const float* b_conv  = (const float*)d_in[6];
    const float* w_obj   = (const float*)d_in[7];
    const float* b_obj   = (const float*)d_in[8];
    const float* w_delta = (const float*)d_in[9];
    const float* b_delta = (const float*)d_in[10];

    static const double sizesT[5] = {32.0, 64.0, 128.0, 256.0, 512.0};
    static const double ratios[3] = {0.5, 1.0, 2.0};
    AnchorP ap;
    for (int l = 0; l < 5; l++) {
        double area = sizesT[l] * sizesT[l];
        for (int a = 0; a < 3; a++) {
            double w = sqrt(area / ratios[a]);
            double h = w * ratios[a];
            ap.cw[l * 3 + a] = -w / 2.0;
            ap.ch[l * 3 + a] = -h / 2.0;
        }
    }

    conv3x3_relu_all<<<PERSIST_CTAS, 256>>>(feats, w_conv, b_conv);
    head_all<<<dim3(341, NIMG), 256>>>(w_obj, b_obj, w_delta, b_delta, ap);

    init_select<<<10, 256>>>();
    for (int r = 0; r < 4; r++) {
        hist_kernel<<<dim3(32, NIMG, 5), 256>>>(r);
        pick_kernel<<<10, 256>>>(r);
    }
    compact_kernel<<<dim3(NIMG, 5), 1024>>>();

    cudaFuncSetAttribute(sort_kernel, cudaFuncAttributeMaxDynamicSharedMemorySize, 65536);
    sort_kernel<<<NIMG, 1024, 65536>>>();
    iou_kernel<<<dim3(19, 149, NIMG), 256>>>();
    nms_scan<<<NIMG, 32>>>((float*)d_out);
}

// round 10
// speedup vs baseline: 1.4237x; 1.0163x over previous
#include <cuda_runtime.h>
#include <math.h>
#include <stdint.h>

#define NIMG   2
#define TCAND  4768
#define NWORDS 149
#define STOT   261888
#define SCALE_CLAMP 4.135166556742356f

// ------------------ static device scratch ------------------
__device__ float    g_scores[NIMG * STOT];
__device__ float4   g_boxes [NIMG * STOT];
__device__ unsigned g_hist[10 * 256];
__device__ unsigned g_prefix[10];
__device__ unsigned g_krem[10];
__device__ unsigned g_kth[10];
__device__ unsigned g_needed[10];
__device__ float    g_cand_s[NIMG * TCAND];
__device__ float4   g_cand_b[NIMG * TCAND];
__device__ float    g_sorted_s[NIMG * TCAND];
__device__ float4   g_sorted_b[NIMG * TCAND];
__device__ float4   g_sorted_ob[NIMG * TCAND];
__device__ unsigned g_validw[NIMG * NWORDS];
__device__ unsigned g_mask[NIMG * TCAND * NWORDS];

// ------------------ level tables ------------------
__constant__ int   c_H[5]      = {256, 128, 64, 32, 16};
__constant__ int   c_HW[5]     = {65536, 16384, 4096, 1024, 256};
__constant__ float c_stride[5] = {4.f, 8.f, 16.f, 32.f, 64.f};
__constant__ int   c_soff[5]   = {0, 196608, 245760, 258048, 261120};
__constant__ int   c_L[5]      = {196608, 49152, 12288, 3072, 768};
__constant__ int   c_k[5]      = {1000, 1000, 1000, 1000, 768};

struct Feats { const float* p[5]; };
struct AnchorP { double cw[15]; double ch[15]; };

// ------------------ helpers ------------------
__device__ __forceinline__ unsigned f2key(float f) {
    unsigned u = __float_as_uint(f);
    return (u & 0x80000000u) ? ~u : (u | 0x80000000u);
}
__device__ __forceinline__ float clip1024(float v) { return fminf(fmaxf(v, 0.f), 1024.f); }
__device__ __forceinline__ void ffma2(unsigned long long& d, unsigned long long a, unsigned long long b) {
    asm("fma.rn.f32x2 %0, %1, %2, %0;" : "+l"(d) : "l"(a), "l"(b));
}
__device__ __forceinline__ unsigned long long dup2(float x) {
    unsigned long long r;
    asm("mov.b64 %0, {%1, %1};" : "=l"(r) : "f"(x));
    return r;
}
__device__ __forceinline__ float2 unpack2(unsigned long long v) {
    float2 r;
    asm("mov.b64 {%0, %1}, %2;" : "=f"(r.x), "=f"(r.y) : "l"(v));
    return r;
}

// smem layout (floats):
// As [2][16][256] @ 0          (8192)
// Bs [2][16][128] @ 8192       (4096)
// T  [256][131]   @ 12288      (33536)
// sw [15][256]    @ 45824      (3840)   total 49664 floats = 198656 B
#define SM_BS 8192
#define SM_T  12288
#define SM_SW 45824
#define TSTRIDE 131
#define CONV_SMEM_B (49664 * 4)

// ------------------ fused FFMA2 conv3x3 + head (+anchor decode) ------------------
// block tile: 256 co x 128 px, thread tile 16 co (8 f32x2 pairs) x 8 px, BK=16.
// grid: x = 682 pixel-tiles (512,128,32,8,2), y = img
__global__ __launch_bounds__(256, 1) void conv_head_all(
    Feats feats, const float* __restrict__ wgt, const float* __restrict__ bias,
    const float* __restrict__ w_obj, const float* __restrict__ b_obj,
    const float* __restrict__ w_delta, const float* __restrict__ b_delta,
    AnchorP ap)
{
    extern __shared__ __align__(16) float sm[];
    float* As = sm;
    float* Bs = sm + SM_BS;
    float* T  = sm + SM_T;
    float* sw = sm + SM_SW;

    const int tid = threadIdx.x;
    const int tx = tid & 15, ty = tid >> 4;

    // head weights -> smem (same values/layout as head_all's sw)
    for (int i = tid; i < 15 * 256; i += 256) {
        int row = i >> 8, c = i & 255;
        sw[i] = (row < 3) ? w_obj[row * 256 + c] : w_delta[(row - 3) * 256 + c];
    }

    int bx = blockIdx.x;
    int lvl, pt;
    if      (bx < 512) { lvl = 0; pt = bx; }
    else if (bx < 640) { lvl = 1; pt = bx - 512; }
    else if (bx < 672) { lvl = 2; pt = bx - 640; }
    else if (bx < 680) { lvl = 3; pt = bx - 672; }
    else               { lvl = 4; pt = bx - 680; }
    const int W  = c_H[lvl];
    const int HW = c_HW[lvl];
    const int n  = blockIdx.y;
    const int p0 = pt * 128;
    const float* inN = feats.p[lvl] + (size_t)n * 256 * HW;

    unsigned long long acc2[8][8];
#pragma unroll
    for (int i = 0; i < 8; i++)
#pragma unroll
        for (int j = 0; j < 8; j++) acc2[i][j] = 0ULL;

    // producer roles (BK=16)
    const int ppB  = tid & 127;
    const int kkB0 = (tid >> 7) * 8;     // 0 or 8
    const float* wrow = wgt + (size_t)tid * 2304;
    const int p   = p0 + ppB;
    const int y0p = p / W;
    const int x0p = p - y0p * W;

    float4 avq[4];
    float  bv[8];

    // ---- prefetch chunk 0 ----
#pragma unroll
    for (int r = 0; r < 4; r++)
        avq[r] = *reinterpret_cast<const float4*>(wrow + r * 4);
#pragma unroll
    for (int q = 0; q < 8; q++) {
        int k  = kkB0 + q;
        int ci = k / 9;
        int rr = k - ci * 9;
        int ky = rr / 3;
        int kx = rr - ky * 3;
        int yy = y0p + ky - 1;
        int xx = x0p + kx - 1;
        float v = 0.f;
        if ((unsigned)yy < (unsigned)W && (unsigned)xx < (unsigned)W)
            v = inN[(size_t)ci * HW + yy * W + xx];
        bv[q] = v;
    }
    {
#pragma unroll
        for (int r = 0; r < 4; r++) {
            float wv[4] = {avq[r].x, avq[r].y, avq[r].z, avq[r].w};
#pragma unroll
            for (int q = 0; q < 4; q++) As[(r * 4 + q) * 256 + tid] = wv[q];
        }
#pragma unroll
        for (int q = 0; q < 8; q++) Bs[(kkB0 + q) * 128 + ppB] = bv[q];
    }
    __syncthreads();

    for (int c0 = 0; c0 < 144; c0++) {
        const int s = c0 & 1;
        const bool more = (c0 + 1) < 144;
        if (more) {
            const float* w2 = wrow + (c0 + 1) * 16;
#pragma unroll
            for (int r = 0; r < 4; r++)
                avq[r] = *reinterpret_cast<const float4*>(w2 + r * 4);
#pragma unroll
            for (int q = 0; q < 8; q++) {
                int k  = (c0 + 1) * 16 + kkB0 + q;
                int ci = k / 9;
                int rr = k - ci * 9;
                int ky = rr / 3;
                int kx = rr - ky * 3;
                int yy = y0p + ky - 1;
                int xx = x0p + kx - 1;
                float v = 0.f;
                if ((unsigned)yy < (unsigned)W && (unsigned)xx < (unsigned)W)
                    v = inN[(size_t)ci * HW + yy * W + xx];
                bv[q] = v;
            }
        }
        // ---- compute stage s (k ascending: bit-identical accumulation order) ----
        const float* Ab = As + s * 16 * 256;
        const float* Bb = Bs + s * 16 * 128;
#pragma unroll
        for (int kk = 0; kk < 16; kk++) {
            unsigned long long a2[8];
#pragma unroll
            for (int q = 0; q < 4; q++) {
                ulonglong2 tt = *reinterpret_cast<const ulonglong2*>(&Ab[kk * 256 + ty * 16 + q * 4]);
                a2[2 * q] = tt.x; a2[2 * q + 1] = tt.y;
            }
            float4 bq0 = *reinterpret_cast<const float4*>(&Bb[kk * 128 + tx * 4]);
            float4 bq1 = *reinterpret_cast<const float4*>(&Bb[kk * 128 + 64 + tx * 4]);
            unsigned long long b2[8];
            b2[0] = dup2(bq0.x); b2[1] = dup2(bq0.y);
            b2[2] = dup2(bq0.z); b2[3] = dup2(bq0.w);
            b2[4] = dup2(bq1.x); b2[5] = dup2(bq1.y);
            b2[6] = dup2(bq1.z); b2[7] = dup2(bq1.w);
#pragma unroll
            for (int i = 0; i < 8; i++)
#pragma unroll
                for (int j = 0; j < 8; j++)
                    ffma2(acc2[i][j], a2[i], b2[j]);
        }
        if (more) {
            float* Ad = As + (s ^ 1) * 16 * 256;
            float* Bd = Bs + (s ^ 1) * 16 * 128;
#pragma unroll
            for (int r = 0; r < 4; r++) {
                float wv[4] = {avq[r].x, avq[r].y, avq[r].z, avq[r].w};
#pragma unroll
                for (int q = 0; q < 4; q++) Ad[(r * 4 + q) * 256 + tid] = wv[q];
            }
#pragma unroll
            for (int q = 0; q < 8; q++) Bd[(kkB0 + q) * 128 + ppB] = bv[q];
        }
        __syncthreads();
    }

    // ---- epilogue: bias + relu -> smem T[co][px] (stride 131, conflict-free) ----
#pragma unroll
    for (int i = 0; i < 8; i++) {
        int co = ty * 16 + 2 * i;
        float bb0 = bias[co], bb1 = bias[co + 1];
        float* t0 = T + (size_t)co * TSTRIDE;
        float* t1 = t0 + TSTRIDE;
#pragma unroll
        for (int j = 0; j < 8; j++) {
            float2 v = unpack2(acc2[i][j]);
            int px = (j < 4) ? (tx * 4 + j) : (64 + tx * 4 + (j - 4));
            t0[px] = fmaxf(v.x + bb0, 0.f);
            t1[px] = fmaxf(v.y + bb1, 0.f);
        }
    }
    __syncthreads();

    // ---- head: exact head_all arithmetic (c ascending 0..255, same fmaf chain) ----
    if (tid < 128) {
        const int px = tid;
        const int pg = p0 + px;
        float acc[15];
#pragma unroll
        for (int i = 0; i < 15; i++) acc[i] = 0.f;
        for (int c = 0; c < 256; c++) {
            float v = T[(size_t)c * TSTRIDE + px];
#pragma unroll
            for (int i = 0; i < 15; i++) acc[i] = fmaf(v, sw[i * 256 + c], acc[i]);
        }
        const float stride = c_stride[lvl];
        float gx = (float)(pg % W) * stride;
        float gy = (float)(pg / W) * stride;
#pragma unroll
        for (int a = 0; a < 3; a++) {
            float s  = acc[a] + b_obj[a];
            float dx = acc[3 + a * 4 + 0] + b_delta[a * 4 + 0];
            float dy = acc[3 + a * 4 + 1] + b_delta[a * 4 + 1];
            float dw = fminf(acc[3 + a * 4 + 2] + b_delta[a * 4 + 2], SCALE_CLAMP);
            float dh = fminf(acc[3 + a * 4 + 3] + b_delta[a * 4 + 3], SCALE_CLAMP);
            double CW = ap.cw[lvl * 3 + a], CH = ap.ch[lvl * 3 + a];
            float x0 = (float)((double)gx + CW);
            float x1 = (float)((double)gx - CW);
            float y0 = (float)((double)gy + CH);
            float y1 = (float)((double)gy - CH);
            float aw = x1 - x0, ah = y1 - y0;
            float acx = x0 + 0.5f * aw, acy = y0 + 0.5f * ah;
            float pcx = dx * aw + acx;
            float pcy = dy * ah + acy;
            float pw = expf(dw) * aw;
            float ph = expf(dh) * ah;
            float4 bx4;
            bx4.x = clip1024(pcx - 0.5f * pw);
            bx4.y = clip1024(pcy - 0.5f * ph);
            bx4.z = clip1024(pcx + 0.5f * pw);
            bx4.w = clip1024(pcy + 0.5f * ph);
            int idx = n * STOT + c_soff[lvl] + pg * 3 + a;
            g_scores[idx] = s;
            g_boxes[idx]  = bx4;
        }
    }
}

// ------------------ level-parallel radix-select ------------------
__global__ void init_select() {
    int s = blockIdx.x;
    if (threadIdx.x == 0) { g_prefix[s] = 0; g_krem[s] = (unsigned)c_k[s >> 1]; }
    g_hist[s * 256 + threadIdx.x] = 0;
}

__global__ void hist_kernel(int round) {
    __shared__ unsigned sh[256];
    int n = blockIdx.y, lvl = blockIdx.z;
    int s = lvl * 2 + n;
    sh[threadIdx.x] = 0;
    __syncthreads();
    unsigned pfx = g_prefix[s];
    int shift = 24 - 8 * round;
    unsigned maskhi = (round == 0) ? 0u : (0xFFFFFFFFu << (shift + 8));
    int L = c_L[lvl];
    const float* sc = g_scores + n * STOT + c_soff[lvl];
    for (int i = blockIdx.x * blockDim.x + threadIdx.x; i < L; i += gridDim.x * blockDim.x) {
        unsigned key = f2key(sc[i]);
        if (((key ^ pfx) & maskhi) == 0)
            atomicAdd(&sh[(key >> shift) & 255], 1u);
    }
    __syncthreads();
    if (sh[threadIdx.x]) atomicAdd(&g_hist[s * 256 + threadIdx.x], sh[threadIdx.x]);
}

__global__ void pick_kernel(int round) {
    int s = blockIdx.x;
    __shared__ unsigned h[256];
    h[threadIdx.x] = g_hist[s * 256 + threadIdx.x];
    __syncthreads();
    g_hist[s * 256 + threadIdx.x] = 0;
    if (threadIdx.x == 0) {
        int shift = 24 - 8 * round;
        unsigned kr = g_krem[s];
        unsigned cum = 0;
        int bin = 255;
        for (; bin > 0; bin--) {
            unsigned c = h[bin];
            if (cum + c >= kr) break;
            cum += c;
        }
        kr -= cum;
        unsigned pfx = g_prefix[s] | ((unsigned)bin << shift);
        g_prefix[s] = pfx;
        g_krem[s] = kr;
        if (round == 3) { g_kth[s] = pfx; g_needed[s] = kr; }
    }
}

// ------------------ compaction: exact top-k SET (ties -> lowest index) ------------------
__global__ __launch_bounds__(1024) void compact_kernel() {
    int n = blockIdx.x, lvl = blockIdx.y;
    int s = lvl * 2 + n;
    int L = c_L[lvl], k = c_k[lvl], lvl_off = lvl * 1000;
    unsigned kth = g_kth[s];
    int needed = (int)g_needed[s];
    int G = k - needed;
    const float* scp = g_scores + n * STOT + c_soff[lvl];
    const float4* bxp = g_boxes + n * STOT + c_soff[lvl];

    __shared__ unsigned wg[32], we[32];
    __shared__ int baseg, basee, totg, tote;
    if (threadIdx.x == 0) { baseg = 0; basee = 0; }
    __syncthreads();
    int lane = threadIdx.x & 31, w = threadIdx.x >> 5;

    for (int start = 0; start < L; start += 1024) {
        int i = start + threadIdx.x;
        bool gt = false, eq = false;
        float sc = 0.f;
        if (i < L) {
            sc = scp[i];
            unsigned key = f2key(sc);
            gt = key > kth;
            eq = (key == kth);
        }
        unsigned bg = __ballot_sync(0xffffffffu, gt);
        unsigned be = __ballot_sync(0xffffffffu, eq);
        if (lane == 0) { wg[w] = __popc(bg); we[w] = __popc(be); }
        __syncthreads();
        if (threadIdx.x < 32) {
            unsigned vg = wg[threadIdx.x], ve = we[threadIdx.x];
            unsigned ig = vg, ie = ve;
#pragma unroll
            for (int o = 1; o < 32; o <<= 1) {
                unsigned tg = __shfl_up_sync(0xffffffffu, ig, o);
                unsigned te = __shfl_up_sync(0xffffffffu, ie, o);
                if ((int)threadIdx.x >= o) { ig += tg; ie += te; }
            }
            wg[threadIdx.x] = ig - vg;
            we[threadIdx.x] = ie - ve;
            if (threadIdx.x == 31) { totg = (int)ig; tote = (int)ie; }
        }
        __syncthreads();
        if (gt) {
            int pos = baseg + (int)wg[w] + __popc(bg & ((1u << lane) - 1));
            g_cand_s[n * TCAND + lvl_off + pos] = sc;
            g_cand_b[n * TCAND + lvl_off + pos] = bxp[i];
        }
        if (eq) {
            int rank = basee + (int)we[w] + __popc(be & ((1u << lane) - 1));
            if (rank < needed) {
                int pos = G + rank;
                g_cand_s[n * TCAND + lvl_off + pos] = sc;
                g_cand_b[n * TCAND + lvl_off + pos] = bxp[i];
            }
        }
        __syncthreads();
        if (threadIdx.x == 0) { baseg += totg; basee += tote; }
        __syncthreads();
    }
}

// ------------------ per-image bitonic sort (score desc, idx asc) ------------------
__global__ __launch_bounds__(1024) void sort_kernel() {
    extern __shared__ unsigned long long keys[];
    int n = blockIdx.x;
    for (int i = threadIdx.x; i < 8192; i += 1024) {
        unsigned long long kk;
        if (i < TCAND) {
            unsigned sk = f2key(g_cand_s[n * TCAND + i]);
            kk = ((unsigned long long)(~sk) << 32) | (unsigned)i;
        } else kk = ~0ULL;
        keys[i] = kk;
    }
    for (int k = 2; k <= 8192; k <<= 1) {
        for (int j = k >> 1; j > 0; j >>= 1) {
            __syncthreads();
            for (int i = threadIdx.x; i < 8192; i += 1024) {
                int ixj = i ^ j;
                if (ixj > i) {
                    unsigned long long a = keys[i], b = keys[ixj];
                    bool up = ((i & k) == 0);
                    if ((a > b) == up) { keys[i] = b; keys[ixj] = a; }
                }
            }
        }
    }
    __syncthreads();
    for (int i = threadIdx.x; i < TCAND; i += 1024) {
        int j = (int)(unsigned)(keys[i] & 0xffffffffu);
        float s = g_cand_s[n * TCAND + j];
        float4 b = g_cand_b[n * TCAND + j];
        int lvl = (j < 4000) ? (j / 1000) : 4;
        float off = (float)lvl * 1025.0f;
        float4 ob = make_float4(b.x + off, b.y + off, b.z + off, b.w + off);
        g_sorted_s[n * TCAND + i] = s;
        g_sorted_b[n * TCAND + i] = b;
        g_sorted_ob[n * TCAND + i] = ob;
        bool valid = (b.z - b.x > 0.f) && (b.w - b.y > 0.f);
        unsigned bal = __ballot_sync(0xffffffffu, valid);
        if ((threadIdx.x & 31) == 0) g_validw[n * NWORDS + (i >> 5)] = bal;
    }
}

// ------------------ IoU suppression bit-matrix (i-tiled, j > i only) ------------------
__global__ __launch_bounds__(256) void iou_kernel() {
    __shared__ float4 sbi[32];
    int n  = blockIdx.z;
    int i0 = blockIdx.y * 32;
    int j  = blockIdx.x * 256 + threadIdx.x;

    if (threadIdx.x < 32) {
        int i = i0 + threadIdx.x;
        sbi[threadIdx.x] = (i < TCAND) ? g_sorted_ob[n * TCAND + i]
                                       : make_float4(0.f, 0.f, 0.f, 0.f);
    }
    __syncthreads();

    float4 bj = make_float4(0.f, 0.f, 0.f, 0.f);
    if (j < TCAND) bj = g_sorted_ob[n * TCAND + j];
    float areaj = (bj.z - bj.x) * (bj.w - bj.y);
    int wq = j >> 5;

#pragma unroll 4
    for (int ii = 0; ii < 32; ii++) {
        int i = i0 + ii;
        if (i >= TCAND) break;
        float4 bi = sbi[ii];
        bool sup = false;
        if (j < TCAND && j > i) {
            float areai = (bi.z - bi.x) * (bi.w - bi.y);
            float ltx = fmaxf(bi.x, bj.x), lty = fmaxf(bi.y, bj.y);
            float rbx = fminf(bi.z, bj.z), rby = fminf(bi.w, bj.w);
            float iw = fmaxf(rbx - ltx, 0.f), ih = fmaxf(rby - lty, 0.f);
            float inter = iw * ih;
            float uni = areai + areaj - inter;
            float iou = (uni > 0.f) ? (inter / uni) : 0.f;
            sup = iou > 0.7f;
        }
        unsigned bal = __ballot_sync(0xffffffffu, sup);
        if ((threadIdx.x & 31) == 0 && wq < NWORDS)
            g_mask[((size_t)n * TCAND + i) * NWORDS + wq] = bal;
    }
}

// ------------------ sequential greedy scan + ordered emission (1 warp / image) ------------------
__global__ void nms_scan(float* __restrict__ out) {
    int n = blockIdx.x;
    int lane = threadIdx.x;
    unsigned keep[5];
#pragma unroll
    for (int q = 0; q < 5; q++) {
        int w = lane * 5 + q;
        keep[q] = (w < NWORDS) ? 0xFFFFFFFFu : 0u;
    }
    const unsigned* mask = g_mask + (size_t)n * TCAND * NWORDS;
    const int NCH = TCAND / 8;
    unsigned cur[8][5], nxt[8][5];
#pragma unroll
    for (int t = 0; t < 8; t++)
#pragma unroll
        for (int q = 0; q < 5; q++) {
            int w = lane * 5 + q;
            cur[t][q] = (w < NWORDS) ? mask[(size_t)t * NWORDS + w] : 0u;
        }
    for (int c = 0; c < NCH; c++) {
        if (c + 1 < NCH) {
            int base = (c + 1) * 8;
#pragma unroll
            for (int t = 0; t < 8; t++)
#pragma unroll
                for (int q = 0; q < 5; q++) {
                    int w = lane * 5 + q;
                    nxt[t][q] = (w < NWORDS) ? mask[(size_t)(base + t) * NWORDS + w] : 0u;
                }
        }
#pragma unroll
        for (int t = 0; t < 8; t++) {
            int i = c * 8 + t;
            int wi = i >> 5;
            int owner = wi / 5;
            int qi = wi - owner * 5;
            unsigned kw;
            switch (qi) {
                case 0: kw = keep[0]; break;
                case 1: kw = keep[1]; break;
                case 2: kw = keep[2]; break;
                case 3: kw = keep[3]; break;
                default: kw = keep[4]; break;
            }
            unsigned word = __shfl_sync(0xffffffffu, kw, owner);
            if ((word >> (i & 31)) & 1u) {
#pragma unroll
                for (int q = 0; q < 5; q++) keep[q] &= ~cur[t][q];
            }
        }
#pragma unroll
        for (int t = 0; t < 8; t++)
#pragma unroll
            for (int q = 0; q < 5; q++) cur[t][q] = nxt[t][q];
    }
#pragma unroll
    for (int q = 0; q < 5; q++) {
        int w = lane * 5 + q;
        if (w < NWORDS) keep[q] &= g_validw[n * NWORDS + w];
    }
    int mycnt = 0;
#pragma unroll
    for (int q = 0; q < 5; q++) mycnt += __popc(keep[q]);
    int incl = mycnt;
#pragma unroll
    for (int o = 1; o < 32; o <<= 1) {
        int t = __shfl_up_sync(0xffffffffu, incl, o);
        if (lane >= o) incl += t;
    }
    int nk = __shfl_sync(0xffffffffu, incl, 31);
    int run = incl - mycnt;
    float ninf = __int_as_float((int)0xff800000u);
    float* outS = out + 8000;
#pragma unroll
    for (int q = 0; q < 5; q++) {
        int w = lane * 5 + q;
        if (w >= NWORDS) continue;
        unsigned kwv = keep[q];
        for (int b = 0; b < 32; b++) {
            int i = w * 32 + b;
            int ones_before = run + __popc(kwv & ((1u << b) - 1));
            bool kept = (kwv >> b) & 1u;
            int pos = kept ? ones_before : (nk + (i - ones_before));
            if (pos < 1000) {
                float4 bx = g_sorted_b[n * TCAND + i];
                float* ob = out + ((size_t)n * 1000 + pos) * 4;
                ob[0] = bx.x; ob[1] = bx.y; ob[2] = bx.z; ob[3] = bx.w;
                outS[n * 1000 + pos] = kept ? g_sorted_s[n * TCAND + i] : ninf;
            }
        }
        run += __popc(kwv);
    }
}

// ------------------ launch ------------------
extern "C" void kernel_launch(void* const* d_in, const int* in_sizes, int n_in,
                              void* d_out, int out_size) {
    (void)in_sizes; (void)n_in; (void)out_size;
    Feats feats;
    for (int i = 0; i < 5; i++) feats.p[i] = (const float*)d_in[i];
    const float* w_conv  = (const float*)d_in[5];
    const float* b_conv  = (const float*)d_in[6];
    const float* w_obj   = (const float*)d_in[7];
    const float* b_obj   = (const float*)d_in[8];
    const float* w_delta = (const float*)d_in[9];
    const float* b_delta = (const float*)d_in[10];

    static const double sizesT[5] = {32.0, 64.0, 128.0, 256.0, 512.0};
    static const double ratios[3] = {0.5, 1.0, 2.0};
    AnchorP ap;
    for (int l = 0; l < 5; l++) {
        double area = sizesT[l] * sizesT[l];
        for (int a = 0; a < 3; a++) {
            double w = sqrt(area / ratios[a]);
            double h = w * ratios[a];
            ap.cw[l * 3 + a] = -w / 2.0;
            ap.ch[l * 3 + a] = -h / 2.0;
        }
    }

    cudaFuncSetAttribute(conv_head_all, cudaFuncAttributeMaxDynamicSharedMemorySize, CONV_SMEM_B);
    conv_head_all<<<dim3(682, NIMG), 256, CONV_SMEM_B>>>(
        feats, w_conv, b_conv, w_obj, b_obj, w_delta, b_delta, ap);

    init_select<<<10, 256>>>();
    for (int r = 0; r < 4; r++) {
        hist_kernel<<<dim3(32, NIMG, 5), 256>>>(r);
        pick_kernel<<<10, 256>>>(r);
    }
    compact_kernel<<<dim3(NIMG, 5), 1024>>>();

    cudaFuncSetAttribute(sort_kernel, cudaFuncAttributeMaxDynamicSharedMemorySize, 65536);
    sort_kernel<<<NIMG, 1024, 65536>>>();
    iou_kernel<<<dim3(19, 149, NIMG), 256>>>();
    nms_scan<<<NIMG, 32>>>((float*)d_out);
}